// round 1
// baseline (speedup 1.0000x reference)
#include <cuda_runtime.h>
#include <math.h>

#define Bb  2
#define Tt  10
#define Nn  1024
#define Dd  1024
#define NHh 16
#define HDd 64
#define BT  (Bb*Tt)

// ---------------- scratch (static device globals; no allocation) ----------------
__device__ float g_traj[(size_t)Nn * Nn];                 // 0.5 * row-normalized traj
__device__ float g_Q[(size_t)Bb * Nn * Dd];
__device__ float g_K[(size_t)Bb * Nn * Dd];
__device__ float g_V[(size_t)Bb * Nn * Dd];
__device__ float g_S[(size_t)Bb * NHh * Nn * Nn];         // scores, then attn (in place)
__device__ float g_AO[(size_t)Bb * Nn * Dd];              // attention output (b,n,d)

// ---------------- block reductions (256 threads) ----------------
__device__ __forceinline__ float blk_sum(float v) {
    __shared__ float red[8];
    #pragma unroll
    for (int o = 16; o > 0; o >>= 1) v += __shfl_xor_sync(0xffffffffu, v, o);
    int w = threadIdx.x >> 5, l = threadIdx.x & 31;
    if (l == 0) red[w] = v;
    __syncthreads();
    if (w == 0) {
        float r = (l < 8) ? red[l] : 0.0f;
        #pragma unroll
        for (int o = 4; o > 0; o >>= 1) r += __shfl_xor_sync(0xffffffffu, r, o);
        if (l == 0) red[0] = r;
    }
    __syncthreads();
    float out = red[0];
    __syncthreads();
    return out;
}

__device__ __forceinline__ float blk_max(float v) {
    __shared__ float red[8];
    #pragma unroll
    for (int o = 16; o > 0; o >>= 1) v = fmaxf(v, __shfl_xor_sync(0xffffffffu, v, o));
    int w = threadIdx.x >> 5, l = threadIdx.x & 31;
    if (l == 0) red[w] = v;
    __syncthreads();
    if (w == 0) {
        float r = (l < 8) ? red[l] : -INFINITY;
        #pragma unroll
        for (int o = 4; o > 0; o >>= 1) r = fmaxf(r, __shfl_xor_sync(0xffffffffu, r, o));
        if (l == 0) red[0] = r;
    }
    __syncthreads();
    float out = red[0];
    __syncthreads();
    return out;
}

// ---------------- 1) trajectory pairwise similarity ----------------
// e[i,j] = exp( -( mean_bt ||pi-pj|| + min(mean_bt ||qi-qj||, mean_bt ||qi+qj||) ) )
__global__ __launch_bounds__(1024) void traj_kernel(const float* __restrict__ pos,
                                                    const float* __restrict__ quat) {
    __shared__ float Pi[3][BT][32], Pj[3][BT][32];
    __shared__ float Qi[4][BT][32], Qj[4][BT][32];
    int i0 = blockIdx.y * 32, j0 = blockIdx.x * 32;
    int tid = threadIdx.y * 32 + threadIdx.x;

    for (int idx = tid; idx < BT * 32; idx += 1024) {
        int bt = idx >> 5, r = idx & 31;
        size_t pi = ((size_t)bt * Nn + i0 + r) * 3;
        size_t pj = ((size_t)bt * Nn + j0 + r) * 3;
        Pi[0][bt][r] = pos[pi + 0]; Pi[1][bt][r] = pos[pi + 1]; Pi[2][bt][r] = pos[pi + 2];
        Pj[0][bt][r] = pos[pj + 0]; Pj[1][bt][r] = pos[pj + 1]; Pj[2][bt][r] = pos[pj + 2];
        size_t qi = ((size_t)bt * Nn + i0 + r) * 4;
        size_t qj = ((size_t)bt * Nn + j0 + r) * 4;
        Qi[0][bt][r] = quat[qi + 0]; Qi[1][bt][r] = quat[qi + 1];
        Qi[2][bt][r] = quat[qi + 2]; Qi[3][bt][r] = quat[qi + 3];
        Qj[0][bt][r] = quat[qj + 0]; Qj[1][bt][r] = quat[qj + 1];
        Qj[2][bt][r] = quat[qj + 2]; Qj[3][bt][r] = quat[qj + 3];
    }
    __syncthreads();

    int ti = threadIdx.y, tj = threadIdx.x;
    float spd = 0.0f, sqm = 0.0f, sqp = 0.0f;
    #pragma unroll
    for (int bt = 0; bt < BT; bt++) {
        float dx = Pi[0][bt][ti] - Pj[0][bt][tj];
        float dy = Pi[1][bt][ti] - Pj[1][bt][tj];
        float dz = Pi[2][bt][ti] - Pj[2][bt][tj];
        spd += sqrtf(dx * dx + dy * dy + dz * dz);
        float a0 = Qi[0][bt][ti], a1 = Qi[1][bt][ti], a2 = Qi[2][bt][ti], a3 = Qi[3][bt][ti];
        float b0 = Qj[0][bt][tj], b1 = Qj[1][bt][tj], b2 = Qj[2][bt][tj], b3 = Qj[3][bt][tj];
        float m0 = a0 - b0, m1 = a1 - b1, m2 = a2 - b2, m3 = a3 - b3;
        float p0 = a0 + b0, p1 = a1 + b1, p2 = a2 + b2, p3 = a3 + b3;
        sqm += sqrtf(m0 * m0 + m1 * m1 + m2 * m2 + m3 * m3);
        sqp += sqrtf(p0 * p0 + p1 * p1 + p2 * p2 + p3 * p3);
    }
    float pd = spd * (1.0f / BT);
    float qd = fminf(sqm, sqp) * (1.0f / BT);
    g_traj[(size_t)(i0 + ti) * Nn + (j0 + tj)] = __expf(-(pd + qd));
}

// ---------------- 2) row-normalize traj, fold in the 0.5 bias scale ----------------
__global__ __launch_bounds__(256) void traj_norm_kernel() {
    float* row = g_traj + (size_t)blockIdx.x * Nn;
    float4 v = ((const float4*)row)[threadIdx.x];
    float s = blk_sum(v.x + v.y + v.z + v.w);
    float sc = 0.5f / s;
    v.x *= sc; v.y *= sc; v.z *= sc; v.w *= sc;
    ((float4*)row)[threadIdx.x] = v;
}

// ---------------- shared GEMM body: C[m,n] = sum_k A[m,k]*W[n,k] + bias[n] ----------------
// M = 2048 (grid.y=16), N = 1024 (grid.x=8), K = 1024. 128x128x16 tile, 256 thr, 8x8/thr.
__device__ __forceinline__ void gemm_nt_body(const float* __restrict__ A,
                                             const float* __restrict__ W,
                                             const float* __restrict__ bias,
                                             float* __restrict__ C) {
    __shared__ float As[16][132];
    __shared__ float Bs[16][132];
    const int K = Dd;
    int tid = threadIdx.x;
    int m0 = blockIdx.y * 128, n0 = blockIdx.x * 128;
    int ty = tid >> 4, tx = tid & 15;
    int lr = tid >> 2;           // 0..63
    int lc = (tid & 3) << 2;     // 0,4,8,12

    float acc[8][8];
    #pragma unroll
    for (int i = 0; i < 8; i++)
        #pragma unroll
        for (int j = 0; j < 8; j++) acc[i][j] = 0.0f;

    const float* Ap = A + (size_t)(m0 + lr) * K + lc;
    const float* Wp = W + (size_t)(n0 + lr) * K + lc;

    for (int k0 = 0; k0 < K; k0 += 16) {
        #pragma unroll
        for (int h = 0; h < 2; h++) {
            float4 a = *(const float4*)(Ap + (size_t)h * 64 * K + k0);
            As[lc + 0][lr + h * 64] = a.x; As[lc + 1][lr + h * 64] = a.y;
            As[lc + 2][lr + h * 64] = a.z; As[lc + 3][lr + h * 64] = a.w;
            float4 b = *(const float4*)(Wp + (size_t)h * 64 * K + k0);
            Bs[lc + 0][lr + h * 64] = b.x; Bs[lc + 1][lr + h * 64] = b.y;
            Bs[lc + 2][lr + h * 64] = b.z; Bs[lc + 3][lr + h * 64] = b.w;
        }
        __syncthreads();
        #pragma unroll
        for (int k = 0; k < 16; k++) {
            float a[8], b[8];
            *(float4*)(&a[0]) = *(const float4*)(&As[k][ty * 8]);
            *(float4*)(&a[4]) = *(const float4*)(&As[k][ty * 8 + 4]);
            *(float4*)(&b[0]) = *(const float4*)(&Bs[k][tx * 8]);
            *(float4*)(&b[4]) = *(const float4*)(&Bs[k][tx * 8 + 4]);
            #pragma unroll
            for (int i = 0; i < 8; i++)
                #pragma unroll
                for (int j = 0; j < 8; j++) acc[i][j] += a[i] * b[j];
        }
        __syncthreads();
    }

    #pragma unroll
    for (int i = 0; i < 8; i++) {
        int m = m0 + ty * 8 + i;
        #pragma unroll
        for (int j = 0; j < 8; j += 4) {
            int n = n0 + tx * 8 + j;
            float4 r;
            r.x = acc[i][j + 0] + bias[n + 0];
            r.y = acc[i][j + 1] + bias[n + 1];
            r.z = acc[i][j + 2] + bias[n + 2];
            r.w = acc[i][j + 3] + bias[n + 3];
            *(float4*)(C + (size_t)m * Dd + n) = r;
        }
    }
}

// ---------------- 3) fused QKV projection (grid.z selects output) ----------------
__global__ __launch_bounds__(256) void qkv_gemm(const float* __restrict__ data,
                                                const float* __restrict__ Wq, const float* __restrict__ bq,
                                                const float* __restrict__ Wk, const float* __restrict__ bk,
                                                const float* __restrict__ Wv, const float* __restrict__ bv) {
    const float *W, *bias; float* C;
    if (blockIdx.z == 0)      { W = Wq; bias = bq; C = g_Q; }
    else if (blockIdx.z == 1) { W = Wk; bias = bk; C = g_K; }
    else                      { W = Wv; bias = bv; C = g_V; }
    gemm_nt_body(data, W, bias, C);
}

// ---------------- 6) output projection ----------------
__global__ __launch_bounds__(256) void out_gemm(const float* __restrict__ Wo,
                                                const float* __restrict__ bo,
                                                float* __restrict__ out) {
    gemm_nt_body(g_AO, Wo, bo, out);
}

// ---------------- 4) scores: S = QK^T/8 + traj_bias ----------------
// grid (16,16,32): 64x64 tile per block, K=HD=64
__global__ __launch_bounds__(256) void scores_kernel() {
    __shared__ float Qs[64][68];
    __shared__ float Ks[64][68];
    int bh = blockIdx.z; int b = bh >> 4, h = bh & 15;
    int i0 = blockIdx.y << 6, j0 = blockIdx.x << 6;
    int tid = threadIdx.x;

    const float* Qg = g_Q + ((size_t)b * Nn + i0) * Dd + h * HDd;
    const float* Kg = g_K + ((size_t)b * Nn + j0) * Dd + h * HDd;
    #pragma unroll
    for (int it = 0; it < 4; it++) {
        int r = (tid >> 4) + it * 16;
        int c = (tid & 15) << 2;
        float4 q = *(const float4*)(Qg + (size_t)r * Dd + c);
        Qs[c + 0][r] = q.x; Qs[c + 1][r] = q.y; Qs[c + 2][r] = q.z; Qs[c + 3][r] = q.w;
        float4 k = *(const float4*)(Kg + (size_t)r * Dd + c);
        Ks[c + 0][r] = k.x; Ks[c + 1][r] = k.y; Ks[c + 2][r] = k.z; Ks[c + 3][r] = k.w;
    }
    __syncthreads();

    int ty = tid >> 4, tx = tid & 15;
    float acc[4][4];
    #pragma unroll
    for (int i = 0; i < 4; i++)
        #pragma unroll
        for (int j = 0; j < 4; j++) acc[i][j] = 0.0f;

    #pragma unroll
    for (int k = 0; k < 64; k++) {
        float a[4], bb[4];
        *(float4*)(&a[0])  = *(const float4*)(&Qs[k][ty << 2]);
        *(float4*)(&bb[0]) = *(const float4*)(&Ks[k][tx << 2]);
        #pragma unroll
        for (int i = 0; i < 4; i++)
            #pragma unroll
            for (int j = 0; j < 4; j++) acc[i][j] += a[i] * bb[j];
    }

    float* Sout = g_S + ((size_t)bh * Nn + i0) * Nn + j0;
    const float* tr = g_traj + (size_t)i0 * Nn + j0;
    #pragma unroll
    for (int i = 0; i < 4; i++) {
        int ii = (ty << 2) + i;
        const float* trow = tr + (size_t)ii * Nn + (tx << 2);
        float4 r;
        r.x = acc[i][0] * 0.125f + trow[0];
        r.y = acc[i][1] * 0.125f + trow[1];
        r.z = acc[i][2] * 0.125f + trow[2];
        r.w = acc[i][3] * 0.125f + trow[3];
        *(float4*)(Sout + (size_t)ii * Nn + (tx << 2)) = r;
    }
}

// ---------------- 5) softmax (in place) + head-avg + entropy + certainty ----------------
// one block per (b, i); loops 16 heads; avg row lives in smem
__global__ __launch_bounds__(256) void softmax_kernel(const float* __restrict__ cert,
                                                      float* __restrict__ out_cert) {
    __shared__ float avg[Nn];
    int bi = blockIdx.x;
    int b = bi >> 10, i = bi & 1023;
    int tid = threadIdx.x;

    float4 z = {0.f, 0.f, 0.f, 0.f};
    ((float4*)avg)[tid] = z;

    for (int h = 0; h < NHh; h++) {
        float* row = g_S + (((size_t)(b * NHh + h) * Nn) + i) * Nn;
        float4 v = ((const float4*)row)[tid];
        float m = blk_max(fmaxf(fmaxf(v.x, v.y), fmaxf(v.z, v.w)));
        float4 e;
        e.x = __expf(v.x - m); e.y = __expf(v.y - m);
        e.z = __expf(v.z - m); e.w = __expf(v.w - m);
        float s = blk_sum(e.x + e.y + e.z + e.w);
        float inv = 1.0f / s;
        e.x *= inv; e.y *= inv; e.z *= inv; e.w *= inv;
        ((float4*)row)[tid] = e;
        float4 a = ((float4*)avg)[tid];
        a.x += e.x * (1.0f / NHh); a.y += e.y * (1.0f / NHh);
        a.z += e.z * (1.0f / NHh); a.w += e.w * (1.0f / NHh);
        ((float4*)avg)[tid] = a;
    }

    float4 p = ((const float4*)avg)[tid];
    float hl = 0.0f;
    p.x = fmaxf(p.x, 1e-10f); hl -= p.x * __logf(p.x);
    p.y = fmaxf(p.y, 1e-10f); hl -= p.y * __logf(p.y);
    p.z = fmaxf(p.z, 1e-10f); hl -= p.z * __logf(p.z);
    p.w = fmaxf(p.w, 1e-10f); hl -= p.w * __logf(p.w);
    float H = blk_sum(hl);
    if (tid == 0) {
        // sigmoid(Hmax - H) = 1 / (1 + exp(H - Hmax)), Hmax = ln(1024)
        float sig = 1.0f / (1.0f + __expf(H - 6.9314718055994531f));
        out_cert[bi] = fmaxf(cert[bi], sig);
    }
}

// ---------------- 6) PV: AO[b,i,h*64+d] = sum_j attn[b,h,i,j] * V[b,j,h*64+d] ----------------
// grid (8, 32): 128 rows x 64 cols per block, K-loop over 1024 in steps of 32
__global__ __launch_bounds__(256) void pv_kernel() {
    __shared__ float As[32][132];
    __shared__ float Vs[32][68];
    int bh = blockIdx.y; int b = bh >> 4, h = bh & 15;
    int i0 = blockIdx.x << 7;
    int tid = threadIdx.x;
    int ty = tid >> 4, tx = tid & 15;

    float acc[8][4];
    #pragma unroll
    for (int i = 0; i < 8; i++)
        #pragma unroll
        for (int j = 0; j < 4; j++) acc[i][j] = 0.0f;

    const float* Arow  = g_S + ((size_t)bh * Nn + i0) * Nn;
    const float* Vbase = g_V + (size_t)b * Nn * Dd + h * HDd;

    for (int j0 = 0; j0 < Nn; j0 += 32) {
        #pragma unroll
        for (int it = 0; it < 4; it++) {
            int r = (tid >> 3) + it * 32;
            int c = (tid & 7) << 2;
            float4 a = *(const float4*)(Arow + (size_t)r * Nn + j0 + c);
            As[c + 0][r] = a.x; As[c + 1][r] = a.y; As[c + 2][r] = a.z; As[c + 3][r] = a.w;
        }
        #pragma unroll
        for (int it = 0; it < 2; it++) {
            int r = (tid >> 4) + it * 16;
            int c = (tid & 15) << 2;
            *(float4*)(&Vs[r][c]) = *(const float4*)(Vbase + (size_t)(j0 + r) * Dd + c);
        }
        __syncthreads();
        #pragma unroll
        for (int k = 0; k < 32; k++) {
            float a[8], v[4];
            *(float4*)(&a[0]) = *(const float4*)(&As[k][ty * 8]);
            *(float4*)(&a[4]) = *(const float4*)(&As[k][ty * 8 + 4]);
            *(float4*)(&v[0]) = *(const float4*)(&Vs[k][tx * 4]);
            #pragma unroll
            for (int i = 0; i < 8; i++)
                #pragma unroll
                for (int j = 0; j < 4; j++) acc[i][j] += a[i] * v[j];
        }
        __syncthreads();
    }

    float* O = g_AO + ((size_t)b * Nn + i0) * Dd + h * HDd;
    #pragma unroll
    for (int i = 0; i < 8; i++) {
        float4 r = make_float4(acc[i][0], acc[i][1], acc[i][2], acc[i][3]);
        *(float4*)(O + (size_t)(ty * 8 + i) * Dd + tx * 4) = r;
    }
}

// ---------------- launch ----------------
extern "C" void kernel_launch(void* const* d_in, const int* in_sizes, int n_in,
                              void* d_out, int out_size) {
    const float* data  = (const float*)d_in[0];
    const float* tpos  = (const float*)d_in[1];
    const float* tquat = (const float*)d_in[2];
    const float* cert  = (const float*)d_in[3];
    const float* Wq = (const float*)d_in[4];  const float* bq = (const float*)d_in[5];
    const float* Wk = (const float*)d_in[6];  const float* bk = (const float*)d_in[7];
    const float* Wv = (const float*)d_in[8];  const float* bv = (const float*)d_in[9];
    const float* Wo = (const float*)d_in[10]; const float* bo = (const float*)d_in[11];
    float* out = (float*)d_out;

    traj_kernel<<<dim3(32, 32), dim3(32, 32)>>>(tpos, tquat);
    traj_norm_kernel<<<Nn, 256>>>();
    qkv_gemm<<<dim3(8, 16, 3), 256>>>(data, Wq, bq, Wk, bk, Wv, bv);
    scores_kernel<<<dim3(16, 16, 32), 256>>>();
    softmax_kernel<<<Bb * Nn, 256>>>(cert, out + (size_t)Bb * Nn * Dd);
    pv_kernel<<<dim3(8, 32), 256>>>();
    out_gemm<<<dim3(8, 16), 256>>>(Wo, bo, out);
}

// round 4
// speedup vs baseline: 1.2971x; 1.2971x over previous
#include <cuda_runtime.h>
#include <cuda_bf16.h>
#include <math.h>
#include <stdint.h>

#define Bb  2
#define Tt  10
#define Nn  1024
#define Dd  1024
#define NHh 16
#define HDd 64
#define BT  (Bb*Tt)

// ---------------- scratch (static device globals; no allocation) ----------------
__device__ float g_traj[(size_t)Nn * Nn];
__device__ float g_Q[(size_t)Bb * Nn * Dd];
__device__ float g_K[(size_t)Bb * Nn * Dd];
__device__ float g_V[(size_t)Bb * Nn * Dd];
__device__ float g_S[(size_t)Bb * NHh * Nn * Nn];
__device__ float g_AO[(size_t)Bb * Nn * Dd];

// bf16 hi/lo split operands for tensor-core GEMMs
__device__ __nv_bfloat16 g_dh[(size_t)Bb * Nn * Dd],  g_dl[(size_t)Bb * Nn * Dd];
__device__ __nv_bfloat16 g_w3h[(size_t)3 * Dd * Dd],  g_w3l[(size_t)3 * Dd * Dd];
__device__ __nv_bfloat16 g_woh[(size_t)Dd * Dd],      g_wol[(size_t)Dd * Dd];
__device__ __nv_bfloat16 g_aoh[(size_t)Bb * Nn * Dd], g_aol[(size_t)Bb * Nn * Dd];

// ================= HMMA helpers (sm_80+ features, legal at compute_103) =================
__device__ __forceinline__ uint32_t smem_to_u32(const void* p) {
    uint32_t a;
    asm("{ .reg .u64 t; cvta.to.shared.u64 t, %1; cvt.u32.u64 %0, t; }" : "=r"(a) : "l"(p));
    return a;
}
__device__ __forceinline__ void cp16(uint32_t dst, const void* src) {
    asm volatile("cp.async.cg.shared.global [%0], [%1], 16;" :: "r"(dst), "l"(src));
}
#define CP_COMMIT() asm volatile("cp.async.commit_group;" ::: "memory")
#define CP_WAIT1()  asm volatile("cp.async.wait_group 1;" ::: "memory")
#define CP_WAIT0()  asm volatile("cp.async.wait_group 0;" ::: "memory")

__device__ __forceinline__ void ldsm_x4(uint32_t* r, uint32_t addr) {
    asm volatile("ldmatrix.sync.aligned.m8n8.x4.shared.b16 {%0,%1,%2,%3}, [%4];"
                 : "=r"(r[0]), "=r"(r[1]), "=r"(r[2]), "=r"(r[3]) : "r"(addr));
}
__device__ __forceinline__ void mma_bf16(float* c, const uint32_t* a, uint32_t b0, uint32_t b1) {
    asm volatile(
        "mma.sync.aligned.m16n8k16.row.col.f32.bf16.bf16.f32 "
        "{%0,%1,%2,%3}, {%4,%5,%6,%7}, {%8,%9}, {%0,%1,%2,%3};"
        : "+f"(c[0]), "+f"(c[1]), "+f"(c[2]), "+f"(c[3])
        : "r"(a[0]), "r"(a[1]), "r"(a[2]), "r"(a[3]), "r"(b0), "r"(b1));
}

// ---------------- block reductions (256 threads) ----------------
__device__ __forceinline__ float blk_sum(float v) {
    __shared__ float red[8];
    #pragma unroll
    for (int o = 16; o > 0; o >>= 1) v += __shfl_xor_sync(0xffffffffu, v, o);
    int w = threadIdx.x >> 5, l = threadIdx.x & 31;
    if (l == 0) red[w] = v;
    __syncthreads();
    if (w == 0) {
        float r = (l < 8) ? red[l] : 0.0f;
        #pragma unroll
        for (int o = 4; o > 0; o >>= 1) r += __shfl_xor_sync(0xffffffffu, r, o);
        if (l == 0) red[0] = r;
    }
    __syncthreads();
    float out = red[0];
    __syncthreads();
    return out;
}
__device__ __forceinline__ float blk_max(float v) {
    __shared__ float red[8];
    #pragma unroll
    for (int o = 16; o > 0; o >>= 1) v = fmaxf(v, __shfl_xor_sync(0xffffffffu, v, o));
    int w = threadIdx.x >> 5, l = threadIdx.x & 31;
    if (l == 0) red[w] = v;
    __syncthreads();
    if (w == 0) {
        float r = (l < 8) ? red[l] : -INFINITY;
        #pragma unroll
        for (int o = 4; o > 0; o >>= 1) r = fmaxf(r, __shfl_xor_sync(0xffffffffu, r, o));
        if (l == 0) red[0] = r;
    }
    __syncthreads();
    float out = red[0];
    __syncthreads();
    return out;
}

// ---------------- fp32 -> bf16 hi/lo split ----------------
// sel==5 reads g_AO via its device-side symbol (a __device__ global's address is
// only valid in device code — passing it from host was the round-3 bug).
__global__ __launch_bounds__(256) void split_kernel(const float* __restrict__ s, int sel, int n4) {
    __nv_bfloat16 *hi, *lo;
    const float* src = s;
    switch (sel) {
        case 0: hi = g_dh;             lo = g_dl;             break;
        case 1: hi = g_w3h;            lo = g_w3l;            break;
        case 2: hi = g_w3h + 1048576;  lo = g_w3l + 1048576;  break;
        case 3: hi = g_w3h + 2097152;  lo = g_w3l + 2097152;  break;
        case 4: hi = g_woh;            lo = g_wol;            break;
        default: hi = g_aoh;           lo = g_aol;            src = g_AO; break;
    }
    int i = blockIdx.x * 256 + threadIdx.x;
    if (i >= n4) return;
    float4 x = ((const float4*)src)[i];
    __nv_bfloat16 h0 = __float2bfloat16_rn(x.x), h1 = __float2bfloat16_rn(x.y);
    __nv_bfloat16 h2 = __float2bfloat16_rn(x.z), h3 = __float2bfloat16_rn(x.w);
    __nv_bfloat16 l0 = __float2bfloat16_rn(x.x - __bfloat162float(h0));
    __nv_bfloat16 l1 = __float2bfloat16_rn(x.y - __bfloat162float(h1));
    __nv_bfloat16 l2 = __float2bfloat16_rn(x.z - __bfloat162float(h2));
    __nv_bfloat16 l3 = __float2bfloat16_rn(x.w - __bfloat162float(h3));
    ((__nv_bfloat162*)hi)[i * 2 + 0] = __nv_bfloat162(h0, h1);
    ((__nv_bfloat162*)hi)[i * 2 + 1] = __nv_bfloat162(h2, h3);
    ((__nv_bfloat162*)lo)[i * 2 + 0] = __nv_bfloat162(l0, l1);
    ((__nv_bfloat162*)lo)[i * 2 + 1] = __nv_bfloat162(l2, l3);
}

// ================= HMMA GEMM: C = A·W^T + bias, 3-pass bf16 split =================
// 128x128 CTA tile, 8 warps (4m x 2n), warp tile 32x64, K-chunk 16, cp.async double buffer.
// smem: 2 stages x 4 matrices (Ah,Al,Wh,Wl) x 128 rows x 24 bf16 (16 data + 8 pad) = 49152 B.
__device__ __forceinline__ void hmma_gemm_body(const __nv_bfloat16* __restrict__ Ah,
                                               const __nv_bfloat16* __restrict__ Al,
                                               const __nv_bfloat16* __restrict__ Wh,
                                               const __nv_bfloat16* __restrict__ Wl,
                                               const float* __restrict__ bias,
                                               float* __restrict__ C) {
    __shared__ __nv_bfloat16 sbuf[2][4][128 * 24];
    int tid = threadIdx.x, lane = tid & 31, wid = tid >> 5;
    int wm = wid & 3, wn = wid >> 2;
    int m0 = blockIdx.y << 7, n0 = blockIdx.x << 7;

    const __nv_bfloat16* srcs[4] = {
        Ah + (size_t)m0 * Dd, Al + (size_t)m0 * Dd,
        Wh + (size_t)n0 * Dd, Wl + (size_t)n0 * Dd };

    uint32_t sb[2][4];
    #pragma unroll
    for (int st = 0; st < 2; st++)
        #pragma unroll
        for (int t = 0; t < 4; t++) sb[st][t] = smem_to_u32(&sbuf[st][t][0]);

    int lr = tid >> 1;            // row 0..127
    int lg = tid & 1;             // 16B half of the 32B row

    float acc[2][8][4];
    #pragma unroll
    for (int i = 0; i < 2; i++)
        #pragma unroll
        for (int j = 0; j < 8; j++)
            #pragma unroll
            for (int k = 0; k < 4; k++) acc[i][j][k] = 0.0f;

    // prefetch chunk 0
    #pragma unroll
    for (int t = 0; t < 4; t++)
        cp16(sb[0][t] + lr * 48 + lg * 16, srcs[t] + (size_t)lr * Dd + lg * 8);
    CP_COMMIT();

    int rsel = lane & 15;
    int csel = (lane >> 4) << 3;

    for (int c = 0; c < 64; c++) {
        int st = c & 1;
        if (c < 63) {
            int kc = (c + 1) << 4, nst = st ^ 1;
            #pragma unroll
            for (int t = 0; t < 4; t++)
                cp16(sb[nst][t] + lr * 48 + lg * 16, srcs[t] + (size_t)lr * Dd + kc + lg * 8);
            CP_COMMIT();
            CP_WAIT1();
        } else {
            CP_WAIT0();
        }
        __syncthreads();

        uint32_t ah[2][4], al[2][4], bh[4][4], bl[4][4];
        #pragma unroll
        for (int mb = 0; mb < 2; mb++) {
            int row = wm * 32 + mb * 16 + rsel;
            ldsm_x4(ah[mb], sb[st][0] + (row * 24 + csel) * 2);
            ldsm_x4(al[mb], sb[st][1] + (row * 24 + csel) * 2);
        }
        #pragma unroll
        for (int np = 0; np < 4; np++) {
            int row = wn * 64 + np * 16 + rsel;
            ldsm_x4(bh[np], sb[st][2] + (row * 24 + csel) * 2);
            ldsm_x4(bl[np], sb[st][3] + (row * 24 + csel) * 2);
        }

        #pragma unroll
        for (int mb = 0; mb < 2; mb++) {
            #pragma unroll
            for (int np = 0; np < 4; np++) {
                mma_bf16(acc[mb][2 * np + 0], ah[mb], bh[np][0], bh[np][2]);
                mma_bf16(acc[mb][2 * np + 1], ah[mb], bh[np][1], bh[np][3]);
                mma_bf16(acc[mb][2 * np + 0], ah[mb], bl[np][0], bl[np][2]);
                mma_bf16(acc[mb][2 * np + 1], ah[mb], bl[np][1], bl[np][3]);
                mma_bf16(acc[mb][2 * np + 0], al[mb], bh[np][0], bh[np][2]);
                mma_bf16(acc[mb][2 * np + 1], al[mb], bh[np][1], bh[np][3]);
            }
        }
        __syncthreads();
    }

    // epilogue: fragment -> gmem with bias
    #pragma unroll
    for (int mb = 0; mb < 2; mb++) {
        int r0 = m0 + wm * 32 + mb * 16 + (lane >> 2);
        #pragma unroll
        for (int nb = 0; nb < 8; nb++) {
            int col = n0 + wn * 64 + nb * 8 + ((lane & 3) << 1);
            float b0 = bias[col], b1 = bias[col + 1];
            float2 v0 = make_float2(acc[mb][nb][0] + b0, acc[mb][nb][1] + b1);
            float2 v1 = make_float2(acc[mb][nb][2] + b0, acc[mb][nb][3] + b1);
            *(float2*)(C + (size_t)r0 * Dd + col) = v0;
            *(float2*)(C + (size_t)(r0 + 8) * Dd + col) = v1;
        }
    }
}

__global__ __launch_bounds__(256, 1) void qkv_tc(const float* __restrict__ bq,
                                                 const float* __restrict__ bk,
                                                 const float* __restrict__ bv) {
    int z = blockIdx.z;
    const __nv_bfloat16* Wh = g_w3h + (size_t)z * 1048576;
    const __nv_bfloat16* Wl = g_w3l + (size_t)z * 1048576;
    const float* bias = (z == 0) ? bq : (z == 1) ? bk : bv;
    float* C = (z == 0) ? g_Q : (z == 1) ? g_K : g_V;
    hmma_gemm_body(g_dh, g_dl, Wh, Wl, bias, C);
}

__global__ __launch_bounds__(256, 1) void out_tc(const float* __restrict__ bo,
                                                 float* __restrict__ out) {
    hmma_gemm_body(g_aoh, g_aol, g_woh, g_wol, bo, out);
}

// ---------------- 1) trajectory pairwise similarity ----------------
__global__ __launch_bounds__(1024) void traj_kernel(const float* __restrict__ pos,
                                                    const float* __restrict__ quat) {
    __shared__ float Pi[3][BT][32], Pj[3][BT][32];
    __shared__ float Qi[4][BT][32], Qj[4][BT][32];
    int i0 = blockIdx.y * 32, j0 = blockIdx.x * 32;
    int tid = threadIdx.y * 32 + threadIdx.x;

    for (int idx = tid; idx < BT * 32; idx += 1024) {
        int bt = idx >> 5, r = idx & 31;
        size_t pi = ((size_t)bt * Nn + i0 + r) * 3;
        size_t pj = ((size_t)bt * Nn + j0 + r) * 3;
        Pi[0][bt][r] = pos[pi + 0]; Pi[1][bt][r] = pos[pi + 1]; Pi[2][bt][r] = pos[pi + 2];
        Pj[0][bt][r] = pos[pj + 0]; Pj[1][bt][r] = pos[pj + 1]; Pj[2][bt][r] = pos[pj + 2];
        size_t qi = ((size_t)bt * Nn + i0 + r) * 4;
        size_t qj = ((size_t)bt * Nn + j0 + r) * 4;
        Qi[0][bt][r] = quat[qi + 0]; Qi[1][bt][r] = quat[qi + 1];
        Qi[2][bt][r] = quat[qi + 2]; Qi[3][bt][r] = quat[qi + 3];
        Qj[0][bt][r] = quat[qj + 0]; Qj[1][bt][r] = quat[qj + 1];
        Qj[2][bt][r] = quat[qj + 2]; Qj[3][bt][r] = quat[qj + 3];
    }
    __syncthreads();

    int ti = threadIdx.y, tj = threadIdx.x;
    float spd = 0.0f, sqm = 0.0f, sqp = 0.0f;
    #pragma unroll
    for (int bt = 0; bt < BT; bt++) {
        float dx = Pi[0][bt][ti] - Pj[0][bt][tj];
        float dy = Pi[1][bt][ti] - Pj[1][bt][tj];
        float dz = Pi[2][bt][ti] - Pj[2][bt][tj];
        spd += sqrtf(dx * dx + dy * dy + dz * dz);
        float a0 = Qi[0][bt][ti], a1 = Qi[1][bt][ti], a2 = Qi[2][bt][ti], a3 = Qi[3][bt][ti];
        float b0 = Qj[0][bt][tj], b1 = Qj[1][bt][tj], b2 = Qj[2][bt][tj], b3 = Qj[3][bt][tj];
        float m0 = a0 - b0, m1 = a1 - b1, m2 = a2 - b2, m3 = a3 - b3;
        float p0 = a0 + b0, p1 = a1 + b1, p2 = a2 + b2, p3 = a3 + b3;
        sqm += sqrtf(m0 * m0 + m1 * m1 + m2 * m2 + m3 * m3);
        sqp += sqrtf(p0 * p0 + p1 * p1 + p2 * p2 + p3 * p3);
    }
    float pd = spd * (1.0f / BT);
    float qd = fminf(sqm, sqp) * (1.0f / BT);
    g_traj[(size_t)(i0 + ti) * Nn + (j0 + tj)] = __expf(-(pd + qd));
}

// ---------------- 2) row-normalize traj (folds in 0.5 bias scale) ----------------
__global__ __launch_bounds__(256) void traj_norm_kernel() {
    float* row = g_traj + (size_t)blockIdx.x * Nn;
    float4 v = ((const float4*)row)[threadIdx.x];
    float s = blk_sum(v.x + v.y + v.z + v.w);
    float sc = 0.5f / s;
    v.x *= sc; v.y *= sc; v.z *= sc; v.w *= sc;
    ((float4*)row)[threadIdx.x] = v;
}

// ---------------- 4) scores: S = QK^T/8 + traj_bias (128x128 tile, 8x8/thread) ----------------
__global__ __launch_bounds__(256) void scores_kernel() {
    __shared__ float Qs[32][132];
    __shared__ float Ks[32][132];
    int bh = blockIdx.z, b = bh >> 4, h = bh & 15;
    int i0 = blockIdx.y << 7, j0 = blockIdx.x << 7;
    int tid = threadIdx.x, ty = tid >> 4, tx = tid & 15;

    float acc[8][8];
    #pragma unroll
    for (int i = 0; i < 8; i++)
        #pragma unroll
        for (int j = 0; j < 8; j++) acc[i][j] = 0.0f;

    const float* Qg = g_Q + ((size_t)b * Nn + i0) * Dd + h * HDd;
    const float* Kg = g_K + ((size_t)b * Nn + j0) * Dd + h * HDd;

    #pragma unroll
    for (int kc = 0; kc < HDd; kc += 32) {
        #pragma unroll
        for (int it = 0; it < 4; it++) {
            int idx = tid + (it << 8);
            int row = idx >> 3, c = (idx & 7) << 2;
            float4 q = *(const float4*)(Qg + (size_t)row * Dd + kc + c);
            Qs[c + 0][row] = q.x; Qs[c + 1][row] = q.y; Qs[c + 2][row] = q.z; Qs[c + 3][row] = q.w;
            float4 k = *(const float4*)(Kg + (size_t)row * Dd + kc + c);
            Ks[c + 0][row] = k.x; Ks[c + 1][row] = k.y; Ks[c + 2][row] = k.z; Ks[c + 3][row] = k.w;
        }
        __syncthreads();
        #pragma unroll
        for (int k = 0; k < 32; k++) {
            float a[8], bb[8];
            *(float4*)(&a[0])  = *(const float4*)(&Qs[k][ty * 8]);
            *(float4*)(&a[4])  = *(const float4*)(&Qs[k][ty * 8 + 4]);
            *(float4*)(&bb[0]) = *(const float4*)(&Ks[k][tx * 8]);
            *(float4*)(&bb[4]) = *(const float4*)(&Ks[k][tx * 8 + 4]);
            #pragma unroll
            for (int i = 0; i < 8; i++)
                #pragma unroll
                for (int j = 0; j < 8; j++) acc[i][j] += a[i] * bb[j];
        }
        __syncthreads();
    }

    float* Sout = g_S + ((size_t)bh * Nn + i0) * Nn + j0;
    const float* tr = g_traj + (size_t)i0 * Nn + j0;
    #pragma unroll
    for (int i = 0; i < 8; i++) {
        int ii = ty * 8 + i;
        const float* trow = tr + (size_t)ii * Nn + tx * 8;
        float* srow = Sout + (size_t)ii * Nn + tx * 8;
        #pragma unroll
        for (int j = 0; j < 8; j += 4) {
            float4 r;
            r.x = acc[i][j + 0] * 0.125f + trow[j + 0];
            r.y = acc[i][j + 1] * 0.125f + trow[j + 1];
            r.z = acc[i][j + 2] * 0.125f + trow[j + 2];
            r.w = acc[i][j + 3] * 0.125f + trow[j + 3];
            *(float4*)(srow + j) = r;
        }
    }
}

// ---------------- 5) softmax (in place) + head-avg + entropy + certainty ----------------
__global__ __launch_bounds__(256) void softmax_kernel(const float* __restrict__ cert,
                                                      float* __restrict__ out_cert) {
    __shared__ float avg[Nn];
    int bi = blockIdx.x;
    int b = bi >> 10, i = bi & 1023;
    int tid = threadIdx.x;

    float4 z = {0.f, 0.f, 0.f, 0.f};
    ((float4*)avg)[tid] = z;

    for (int h = 0; h < NHh; h++) {
        float* row = g_S + (((size_t)(b * NHh + h) * Nn) + i) * Nn;
        float4 v = ((const float4*)row)[tid];
        float m = blk_max(fmaxf(fmaxf(v.x, v.y), fmaxf(v.z, v.w)));
        float4 e;
        e.x = __expf(v.x - m); e.y = __expf(v.y - m);
        e.z = __expf(v.z - m); e.w = __expf(v.w - m);
        float s = blk_sum(e.x + e.y + e.z + e.w);
        float inv = 1.0f / s;
        e.x *= inv; e.y *= inv; e.z *= inv; e.w *= inv;
        ((float4*)row)[tid] = e;
        float4 a = ((float4*)avg)[tid];
        a.x += e.x * (1.0f / NHh); a.y += e.y * (1.0f / NHh);
        a.z += e.z * (1.0f / NHh); a.w += e.w * (1.0f / NHh);
        ((float4*)avg)[tid] = a;
    }

    float4 p = ((const float4*)avg)[tid];
    float hl = 0.0f;
    p.x = fmaxf(p.x, 1e-10f); hl -= p.x * __logf(p.x);
    p.y = fmaxf(p.y, 1e-10f); hl -= p.y * __logf(p.y);
    p.z = fmaxf(p.z, 1e-10f); hl -= p.z * __logf(p.z);
    p.w = fmaxf(p.w, 1e-10f); hl -= p.w * __logf(p.w);
    float H = blk_sum(hl);
    if (tid == 0) {
        float sig = 1.0f / (1.0f + __expf(H - 6.9314718055994531f));
        out_cert[bi] = fmaxf(cert[bi], sig);
    }
}

// ---------------- 6) PV: AO = attn @ V ----------------
__global__ __launch_bounds__(256) void pv_kernel() {
    __shared__ float As[32][132];
    __shared__ float Vs[32][68];
    int bh = blockIdx.y; int b = bh >> 4, h = bh & 15;
    int i0 = blockIdx.x << 7;
    int tid = threadIdx.x;
    int ty = tid >> 4, tx = tid & 15;

    float acc[8][4];
    #pragma unroll
    for (int i = 0; i < 8; i++)
        #pragma unroll
        for (int j = 0; j < 4; j++) acc[i][j] = 0.0f;

    const float* Arow  = g_S + ((size_t)bh * Nn + i0) * Nn;
    const float* Vbase = g_V + (size_t)b * Nn * Dd + h * HDd;

    for (int j0 = 0; j0 < Nn; j0 += 32) {
        #pragma unroll
        for (int it = 0; it < 4; it++) {
            int r = (tid >> 3) + it * 32;
            int c = (tid & 7) << 2;
            float4 a = *(const float4*)(Arow + (size_t)r * Nn + j0 + c);
            As[c + 0][r] = a.x; As[c + 1][r] = a.y; As[c + 2][r] = a.z; As[c + 3][r] = a.w;
        }
        #pragma unroll
        for (int it = 0; it < 2; it++) {
            int r = (tid >> 4) + it * 16;
            int c = (tid & 15) << 2;
            *(float4*)(&Vs[r][c]) = *(const float4*)(Vbase + (size_t)(j0 + r) * Dd + c);
        }
        __syncthreads();
        #pragma unroll
        for (int k = 0; k < 32; k++) {
            float a[8], v[4];
            *(float4*)(&a[0]) = *(const float4*)(&As[k][ty * 8]);
            *(float4*)(&a[4]) = *(const float4*)(&As[k][ty * 8 + 4]);
            *(float4*)(&v[0]) = *(const float4*)(&Vs[k][tx * 4]);
            #pragma unroll
            for (int i = 0; i < 8; i++)
                #pragma unroll
                for (int j = 0; j < 4; j++) acc[i][j] += a[i] * v[j];
        }
        __syncthreads();
    }

    float* O = g_AO + ((size_t)b * Nn + i0) * Dd + h * HDd;
    #pragma unroll
    for (int i = 0; i < 8; i++) {
        float4 r = make_float4(acc[i][0], acc[i][1], acc[i][2], acc[i][3]);
        *(float4*)(O + (size_t)(ty * 8 + i) * Dd + tx * 4) = r;
    }
}

// ---------------- launch ----------------
extern "C" void kernel_launch(void* const* d_in, const int* in_sizes, int n_in,
                              void* d_out, int out_size) {
    const float* data  = (const float*)d_in[0];
    const float* tpos  = (const float*)d_in[1];
    const float* tquat = (const float*)d_in[2];
    const float* cert  = (const float*)d_in[3];
    const float* Wq = (const float*)d_in[4];  const float* bq = (const float*)d_in[5];
    const float* Wk = (const float*)d_in[6];  const float* bk = (const float*)d_in[7];
    const float* Wv = (const float*)d_in[8];  const float* bv = (const float*)d_in[9];
    const float* Wo = (const float*)d_in[10]; const float* bo = (const float*)d_in[11];
    float* out = (float*)d_out;

    // bf16 hi/lo splits for tensor-core GEMM operands (harness pointers only)
    split_kernel<<<2048, 256>>>(data, 0, 524288);
    split_kernel<<<1024, 256>>>(Wq,   1, 262144);
    split_kernel<<<1024, 256>>>(Wk,   2, 262144);
    split_kernel<<<1024, 256>>>(Wv,   3, 262144);
    split_kernel<<<1024, 256>>>(Wo,   4, 262144);

    traj_kernel<<<dim3(32, 32), dim3(32, 32)>>>(tpos, tquat);
    traj_norm_kernel<<<Nn, 256>>>();

    qkv_tc<<<dim3(8, 16, 3), 256>>>(bq, bk, bv);
    scores_kernel<<<dim3(8, 8, 32), 256>>>();
    softmax_kernel<<<Bb * Nn, 256>>>(cert, out + (size_t)Bb * Nn * Dd);
    pv_kernel<<<dim3(8, 32), 256>>>();

    split_kernel<<<2048, 256>>>(nullptr, 5, 524288);  // src resolved device-side (g_AO)
    out_tc<<<dim3(8, 16), 256>>>(bo, out);
}

// round 5
// speedup vs baseline: 1.6167x; 1.2464x over previous
#include <cuda_runtime.h>
#include <cuda_bf16.h>
#include <math.h>
#include <stdint.h>

#define Bb  2
#define Tt  10
#define Nn  1024
#define Dd  1024
#define NHh 16
#define HDd 64
#define BT  (Bb*Tt)

// ---------------- scratch (static device globals; no allocation) ----------------
__device__ float g_traj[(size_t)Nn * Nn];
__device__ float g_S[(size_t)Bb * NHh * Nn * Nn];          // scores (fp32, softmax input)

// bf16 hi/lo operand pairs
__device__ __nv_bfloat16 g_dh[(size_t)Bb * Nn * Dd],  g_dl[(size_t)Bb * Nn * Dd];
__device__ __nv_bfloat16 g_w3h[(size_t)3 * Dd * Dd],  g_w3l[(size_t)3 * Dd * Dd];
__device__ __nv_bfloat16 g_woh[(size_t)Dd * Dd],      g_wol[(size_t)Dd * Dd];
__device__ __nv_bfloat16 g_qh[(size_t)Bb * Nn * Dd],  g_ql[(size_t)Bb * Nn * Dd];   // Q/8
__device__ __nv_bfloat16 g_kh[(size_t)Bb * Nn * Dd],  g_kl[(size_t)Bb * Nn * Dd];
__device__ __nv_bfloat16 g_vh[(size_t)Bb * Nn * Dd],  g_vl[(size_t)Bb * Nn * Dd];
__device__ __nv_bfloat16 g_ph[(size_t)Bb * NHh * Nn * Nn], g_pl[(size_t)Bb * NHh * Nn * Nn];
__device__ __nv_bfloat16 g_aoh[(size_t)Bb * Nn * Dd], g_aol[(size_t)Bb * Nn * Dd];

// ================= HMMA helpers =================
__device__ __forceinline__ uint32_t smem_to_u32(const void* p) {
    uint32_t a;
    asm("{ .reg .u64 t; cvta.to.shared.u64 t, %1; cvt.u32.u64 %0, t; }" : "=r"(a) : "l"(p));
    return a;
}
__device__ __forceinline__ void cp16(uint32_t dst, const void* src) {
    asm volatile("cp.async.cg.shared.global [%0], [%1], 16;" :: "r"(dst), "l"(src));
}
#define CP_COMMIT() asm volatile("cp.async.commit_group;" ::: "memory")
#define CP_WAIT1()  asm volatile("cp.async.wait_group 1;" ::: "memory")
#define CP_WAIT0()  asm volatile("cp.async.wait_group 0;" ::: "memory")

__device__ __forceinline__ void ldsm_x4(uint32_t* r, uint32_t addr) {
    asm volatile("ldmatrix.sync.aligned.m8n8.x4.shared.b16 {%0,%1,%2,%3}, [%4];"
                 : "=r"(r[0]), "=r"(r[1]), "=r"(r[2]), "=r"(r[3]) : "r"(addr));
}
__device__ __forceinline__ void ldsm_x4_t(uint32_t* r, uint32_t addr) {
    asm volatile("ldmatrix.sync.aligned.m8n8.x4.trans.shared.b16 {%0,%1,%2,%3}, [%4];"
                 : "=r"(r[0]), "=r"(r[1]), "=r"(r[2]), "=r"(r[3]) : "r"(addr));
}
__device__ __forceinline__ void mma_bf16(float* c, const uint32_t* a, uint32_t b0, uint32_t b1) {
    asm volatile(
        "mma.sync.aligned.m16n8k16.row.col.f32.bf16.bf16.f32 "
        "{%0,%1,%2,%3}, {%4,%5,%6,%7}, {%8,%9}, {%0,%1,%2,%3};"
        : "+f"(c[0]), "+f"(c[1]), "+f"(c[2]), "+f"(c[3])
        : "r"(a[0]), "r"(a[1]), "r"(a[2]), "r"(a[3]), "r"(b0), "r"(b1));
}
__device__ __forceinline__ __nv_bfloat162 split_hi2(float a, float b, float* ra, float* rb) {
    __nv_bfloat16 h0 = __float2bfloat16_rn(a), h1 = __float2bfloat16_rn(b);
    *ra = a - __bfloat162float(h0);
    *rb = b - __bfloat162float(h1);
    return __nv_bfloat162(h0, h1);
}

// ---------------- block reductions (256 threads) ----------------
__device__ __forceinline__ float blk_sum(float v) {
    __shared__ float red[8];
    #pragma unroll
    for (int o = 16; o > 0; o >>= 1) v += __shfl_xor_sync(0xffffffffu, v, o);
    int w = threadIdx.x >> 5, l = threadIdx.x & 31;
    if (l == 0) red[w] = v;
    __syncthreads();
    if (w == 0) {
        float r = (l < 8) ? red[l] : 0.0f;
        #pragma unroll
        for (int o = 4; o > 0; o >>= 1) r += __shfl_xor_sync(0xffffffffu, r, o);
        if (l == 0) red[0] = r;
    }
    __syncthreads();
    float out = red[0];
    __syncthreads();
    return out;
}
__device__ __forceinline__ float blk_max(float v) {
    __shared__ float red[8];
    #pragma unroll
    for (int o = 16; o > 0; o >>= 1) v = fmaxf(v, __shfl_xor_sync(0xffffffffu, v, o));
    int w = threadIdx.x >> 5, l = threadIdx.x & 31;
    if (l == 0) red[w] = v;
    __syncthreads();
    if (w == 0) {
        float r = (l < 8) ? red[l] : -INFINITY;
        #pragma unroll
        for (int o = 4; o > 0; o >>= 1) r = fmaxf(r, __shfl_xor_sync(0xffffffffu, r, o));
        if (l == 0) red[0] = r;
    }
    __syncthreads();
    float out = red[0];
    __syncthreads();
    return out;
}

// ---------------- fp32 -> bf16 hi/lo split (inputs only) ----------------
__global__ __launch_bounds__(256) void split_kernel(const float* __restrict__ s, int sel, int n4) {
    __nv_bfloat16 *hi, *lo;
    switch (sel) {
        case 0: hi = g_dh;             lo = g_dl;             break;
        case 1: hi = g_w3h;            lo = g_w3l;            break;
        case 2: hi = g_w3h + 1048576;  lo = g_w3l + 1048576;  break;
        case 3: hi = g_w3h + 2097152;  lo = g_w3l + 2097152;  break;
        default: hi = g_woh;           lo = g_wol;            break;
    }
    int i = blockIdx.x * 256 + threadIdx.x;
    if (i >= n4) return;
    float4 x = ((const float4*)s)[i];
    float r0, r1, r2, r3;
    __nv_bfloat162 h01 = split_hi2(x.x, x.y, &r0, &r1);
    __nv_bfloat162 h23 = split_hi2(x.z, x.w, &r2, &r3);
    ((__nv_bfloat162*)hi)[i * 2 + 0] = h01;
    ((__nv_bfloat162*)hi)[i * 2 + 1] = h23;
    ((__nv_bfloat162*)lo)[i * 2 + 0] = __nv_bfloat162(__float2bfloat16_rn(r0), __float2bfloat16_rn(r1));
    ((__nv_bfloat162*)lo)[i * 2 + 1] = __nv_bfloat162(__float2bfloat16_rn(r2), __float2bfloat16_rn(r3));
}

// ================= HMMA GEMM core (qkv / out projections) =================
// 128x128 CTA tile, 8 warps (4m x 2n), K-chunk 16, cp.async double buffer, 48KB smem.
// mode 0: epilogue writes hi/lo bf16 split of (acc+bias)*scale to Chi/Clo
// mode 1: epilogue writes fp32 (acc+bias) to Cf
__device__ __forceinline__ void hmma_gemm_body(const __nv_bfloat16* __restrict__ Ah,
                                               const __nv_bfloat16* __restrict__ Al,
                                               const __nv_bfloat16* __restrict__ Wh,
                                               const __nv_bfloat16* __restrict__ Wl,
                                               const float* __restrict__ bias,
                                               float scale, int mode,
                                               float* __restrict__ Cf,
                                               __nv_bfloat16* __restrict__ Chi,
                                               __nv_bfloat16* __restrict__ Clo) {
    __shared__ __nv_bfloat16 sbuf[2][4][128 * 24];
    int tid = threadIdx.x, lane = tid & 31, wid = tid >> 5;
    int wm = wid & 3, wn = wid >> 2;
    int m0 = blockIdx.y << 7, n0 = blockIdx.x << 7;

    const __nv_bfloat16* srcs[4] = {
        Ah + (size_t)m0 * Dd, Al + (size_t)m0 * Dd,
        Wh + (size_t)n0 * Dd, Wl + (size_t)n0 * Dd };

    uint32_t sb[2][4];
    #pragma unroll
    for (int st = 0; st < 2; st++)
        #pragma unroll
        for (int t = 0; t < 4; t++) sb[st][t] = smem_to_u32(&sbuf[st][t][0]);

    int lr = tid >> 1, lg = tid & 1;

    float acc[2][8][4];
    #pragma unroll
    for (int i = 0; i < 2; i++)
        #pragma unroll
        for (int j = 0; j < 8; j++)
            #pragma unroll
            for (int k = 0; k < 4; k++) acc[i][j][k] = 0.0f;

    #pragma unroll
    for (int t = 0; t < 4; t++)
        cp16(sb[0][t] + lr * 48 + lg * 16, srcs[t] + (size_t)lr * Dd + lg * 8);
    CP_COMMIT();

    int rsel = lane & 15;
    int csel = (lane >> 4) << 3;

    for (int c = 0; c < 64; c++) {
        int st = c & 1;
        if (c < 63) {
            int kc = (c + 1) << 4, nst = st ^ 1;
            #pragma unroll
            for (int t = 0; t < 4; t++)
                cp16(sb[nst][t] + lr * 48 + lg * 16, srcs[t] + (size_t)lr * Dd + kc + lg * 8);
            CP_COMMIT();
            CP_WAIT1();
        } else {
            CP_WAIT0();
        }
        __syncthreads();

        uint32_t ah[2][4], al[2][4], bh[4][4], bl[4][4];
        #pragma unroll
        for (int mb = 0; mb < 2; mb++) {
            int row = wm * 32 + mb * 16 + rsel;
            ldsm_x4(ah[mb], sb[st][0] + (row * 24 + csel) * 2);
            ldsm_x4(al[mb], sb[st][1] + (row * 24 + csel) * 2);
        }
        #pragma unroll
        for (int np = 0; np < 4; np++) {
            int row = wn * 64 + np * 16 + rsel;
            ldsm_x4(bh[np], sb[st][2] + (row * 24 + csel) * 2);
            ldsm_x4(bl[np], sb[st][3] + (row * 24 + csel) * 2);
        }
        #pragma unroll
        for (int mb = 0; mb < 2; mb++) {
            #pragma unroll
            for (int np = 0; np < 4; np++) {
                mma_bf16(acc[mb][2 * np + 0], ah[mb], bh[np][0], bh[np][2]);
                mma_bf16(acc[mb][2 * np + 1], ah[mb], bh[np][1], bh[np][3]);
                mma_bf16(acc[mb][2 * np + 0], ah[mb], bl[np][0], bl[np][2]);
                mma_bf16(acc[mb][2 * np + 1], ah[mb], bl[np][1], bl[np][3]);
                mma_bf16(acc[mb][2 * np + 0], al[mb], bh[np][0], bh[np][2]);
                mma_bf16(acc[mb][2 * np + 1], al[mb], bh[np][1], bh[np][3]);
            }
        }
        __syncthreads();
    }

    #pragma unroll
    for (int mb = 0; mb < 2; mb++) {
        int r0 = m0 + wm * 32 + mb * 16 + (lane >> 2);
        #pragma unroll
        for (int nb = 0; nb < 8; nb++) {
            int col = n0 + wn * 64 + nb * 8 + ((lane & 3) << 1);
            float b0 = bias[col], b1 = bias[col + 1];
            float x0 = (acc[mb][nb][0] + b0) * scale, x1 = (acc[mb][nb][1] + b1) * scale;
            float x2 = (acc[mb][nb][2] + b0) * scale, x3 = (acc[mb][nb][3] + b1) * scale;
            if (mode == 1) {
                *(float2*)(Cf + (size_t)r0 * Dd + col)       = make_float2(x0, x1);
                *(float2*)(Cf + (size_t)(r0 + 8) * Dd + col) = make_float2(x2, x3);
            } else {
                float l0, l1, l2, l3;
                __nv_bfloat162 h01 = split_hi2(x0, x1, &l0, &l1);
                __nv_bfloat162 h23 = split_hi2(x2, x3, &l2, &l3);
                *(__nv_bfloat162*)(Chi + (size_t)r0 * Dd + col)       = h01;
                *(__nv_bfloat162*)(Chi + (size_t)(r0 + 8) * Dd + col) = h23;
                *(__nv_bfloat162*)(Clo + (size_t)r0 * Dd + col) =
                    __nv_bfloat162(__float2bfloat16_rn(l0), __float2bfloat16_rn(l1));
                *(__nv_bfloat162*)(Clo + (size_t)(r0 + 8) * Dd + col) =
                    __nv_bfloat162(__float2bfloat16_rn(l2), __float2bfloat16_rn(l3));
            }
        }
    }
}

__global__ __launch_bounds__(256, 1) void qkv_tc(const float* __restrict__ bq,
                                                 const float* __restrict__ bk,
                                                 const float* __restrict__ bv) {
    int z = blockIdx.z;
    const __nv_bfloat16* Wh = g_w3h + (size_t)z * 1048576;
    const __nv_bfloat16* Wl = g_w3l + (size_t)z * 1048576;
    const float* bias = (z == 0) ? bq : (z == 1) ? bk : bv;
    __nv_bfloat16* Chi = (z == 0) ? g_qh : (z == 1) ? g_kh : g_vh;
    __nv_bfloat16* Clo = (z == 0) ? g_ql : (z == 1) ? g_kl : g_vl;
    float scale = (z == 0) ? 0.125f : 1.0f;   // fold 1/sqrt(HD) into Q
    hmma_gemm_body(g_dh, g_dl, Wh, Wl, bias, scale, 0, nullptr, Chi, Clo);
}

__global__ __launch_bounds__(256, 1) void out_tc(const float* __restrict__ bo,
                                                 float* __restrict__ out) {
    hmma_gemm_body(g_aoh, g_aol, g_woh, g_wol, bo, 1.0f, 1, out, nullptr, nullptr);
}

// ================= scores: S = (Q/8)·K^T + traj  (HMMA, 64x64 tiles) =================
// grid (16 j, 16 i, 32 bh), 8 warps: wm=i-block(16), wn=j-block(32). smem 36.9KB.
__global__ __launch_bounds__(256, 1) void scores_tc() {
    __shared__ __nv_bfloat16 s_q[2][64 * 72];   // [hi,lo][row 64][72 pad]
    __shared__ __nv_bfloat16 s_k[2][64 * 72];
    int bh = blockIdx.z, b = bh >> 4, h = bh & 15;
    int i0 = blockIdx.y << 6, j0 = blockIdx.x << 6;
    int tid = threadIdx.x, lane = tid & 31, wid = tid >> 5;
    int wm = wid & 3, wn = wid >> 2;

    uint32_t sq[2] = { smem_to_u32(&s_q[0][0]), smem_to_u32(&s_q[1][0]) };
    uint32_t sk[2] = { smem_to_u32(&s_k[0][0]), smem_to_u32(&s_k[1][0]) };

    {   // load 4 matrices of 64x64 bf16 via cp.async
        const __nv_bfloat16* Qh = g_qh + ((size_t)b * Nn + i0) * Dd + h * HDd;
        const __nv_bfloat16* Ql = g_ql + ((size_t)b * Nn + i0) * Dd + h * HDd;
        const __nv_bfloat16* Kh = g_kh + ((size_t)b * Nn + j0) * Dd + h * HDd;
        const __nv_bfloat16* Kl = g_kl + ((size_t)b * Nn + j0) * Dd + h * HDd;
        #pragma unroll
        for (int it = 0; it < 2; it++) {
            int idx = tid + (it << 8);
            int row = idx >> 3, seg = idx & 7;
            size_t go = (size_t)row * Dd + seg * 8;
            uint32_t so = (row * 72 + seg * 8) * 2;
            cp16(sq[0] + so, Qh + go);
            cp16(sq[1] + so, Ql + go);
            cp16(sk[0] + so, Kh + go);
            cp16(sk[1] + so, Kl + go);
        }
        CP_COMMIT();
        CP_WAIT0();
        __syncthreads();
    }

    int rsel = lane & 15, csel = (lane >> 4) << 3;
    float acc[4][4];
    #pragma unroll
    for (int i = 0; i < 4; i++)
        #pragma unroll
        for (int j = 0; j < 4; j++) acc[i][j] = 0.0f;

    #pragma unroll
    for (int kk = 0; kk < 4; kk++) {
        uint32_t ah[4], al[4], bh2[2][4], bl2[2][4];
        int arow = wm * 16 + rsel;
        ldsm_x4(ah, sq[0] + (arow * 72 + kk * 16 + csel) * 2);
        ldsm_x4(al, sq[1] + (arow * 72 + kk * 16 + csel) * 2);
        #pragma unroll
        for (int np = 0; np < 2; np++) {
            int brow = wn * 32 + np * 16 + rsel;
            ldsm_x4(bh2[np], sk[0] + (brow * 72 + kk * 16 + csel) * 2);
            ldsm_x4(bl2[np], sk[1] + (brow * 72 + kk * 16 + csel) * 2);
        }
        #pragma unroll
        for (int np = 0; np < 2; np++) {
            mma_bf16(acc[2 * np + 0], ah, bh2[np][0], bh2[np][2]);
            mma_bf16(acc[2 * np + 1], ah, bh2[np][1], bh2[np][3]);
            mma_bf16(acc[2 * np + 0], ah, bl2[np][0], bl2[np][2]);
            mma_bf16(acc[2 * np + 1], ah, bl2[np][1], bl2[np][3]);
            mma_bf16(acc[2 * np + 0], al, bh2[np][0], bh2[np][2]);
            mma_bf16(acc[2 * np + 1], al, bh2[np][1], bh2[np][3]);
        }
    }

    // epilogue: add traj bias (pre-scaled 0.5/rowsum), write fp32 S
    float* Sout = g_S + (size_t)bh * Nn * Nn;
    #pragma unroll
    for (int nb = 0; nb < 4; nb++) {
        int i  = i0 + wm * 16 + (lane >> 2);
        int j  = j0 + wn * 32 + nb * 8 + ((lane & 3) << 1);
        const float* t0 = g_traj + (size_t)i * Nn + j;
        const float* t1 = g_traj + (size_t)(i + 8) * Nn + j;
        float2 v0 = make_float2(acc[nb][0] + t0[0], acc[nb][1] + t0[1]);
        float2 v1 = make_float2(acc[nb][2] + t1[0], acc[nb][3] + t1[1]);
        *(float2*)(Sout + (size_t)i * Nn + j)       = v0;
        *(float2*)(Sout + (size_t)(i + 8) * Nn + j) = v1;
    }
}

// ---------------- softmax + head-avg + entropy + certainty; writes p as bf16 hi/lo ----------------
__global__ __launch_bounds__(256) void softmax_kernel(const float* __restrict__ cert,
                                                      float* __restrict__ out_cert) {
    __shared__ float avg[Nn];
    int bi = blockIdx.x;
    int b = bi >> 10, i = bi & 1023;
    int tid = threadIdx.x;

    float4 z = {0.f, 0.f, 0.f, 0.f};
    ((float4*)avg)[tid] = z;

    for (int h = 0; h < NHh; h++) {
        size_t base = (((size_t)(b * NHh + h) * Nn) + i) * Nn;
        const float* row = g_S + base;
        float4 v = ((const float4*)row)[tid];
        float m = blk_max(fmaxf(fmaxf(v.x, v.y), fmaxf(v.z, v.w)));
        float4 e;
        e.x = __expf(v.x - m); e.y = __expf(v.y - m);
        e.z = __expf(v.z - m); e.w = __expf(v.w - m);
        float s = blk_sum(e.x + e.y + e.z + e.w);
        float inv = 1.0f / s;
        e.x *= inv; e.y *= inv; e.z *= inv; e.w *= inv;

        float l0, l1, l2, l3;
        __nv_bfloat162 h01 = split_hi2(e.x, e.y, &l0, &l1);
        __nv_bfloat162 h23 = split_hi2(e.z, e.w, &l2, &l3);
        ((__nv_bfloat162*)(g_ph + base))[tid * 2 + 0] = h01;
        ((__nv_bfloat162*)(g_ph + base))[tid * 2 + 1] = h23;
        ((__nv_bfloat162*)(g_pl + base))[tid * 2 + 0] =
            __nv_bfloat162(__float2bfloat16_rn(l0), __float2bfloat16_rn(l1));
        ((__nv_bfloat162*)(g_pl + base))[tid * 2 + 1] =
            __nv_bfloat162(__float2bfloat16_rn(l2), __float2bfloat16_rn(l3));

        float4 a = ((float4*)avg)[tid];
        a.x += e.x * (1.0f / NHh); a.y += e.y * (1.0f / NHh);
        a.z += e.z * (1.0f / NHh); a.w += e.w * (1.0f / NHh);
        ((float4*)avg)[tid] = a;
    }

    float4 p = ((const float4*)avg)[tid];
    float hl = 0.0f;
    p.x = fmaxf(p.x, 1e-10f); hl -= p.x * __logf(p.x);
    p.y = fmaxf(p.y, 1e-10f); hl -= p.y * __logf(p.y);
    p.z = fmaxf(p.z, 1e-10f); hl -= p.z * __logf(p.z);
    p.w = fmaxf(p.w, 1e-10f); hl -= p.w * __logf(p.w);
    float H = blk_sum(hl);
    if (tid == 0) {
        float sig = 1.0f / (1.0f + __expf(H - 6.9314718055994531f));
        out_cert[bi] = fmaxf(cert[bi], sig);
    }
}

// ================= pv: AO = p @ V (HMMA, ldmatrix.trans for V) =================
// grid (16 i-tiles, 32 bh); CTA tile 64i x 64d; j-loop 32 chunks of 32, double-buffered.
// 8 warps: wm=wid&3 (16 i rows), wn=wid>>2 (32 d cols). Epilogue writes AO hi/lo bf16.
__global__ __launch_bounds__(256, 1) void pv_tc() {
    __shared__ __nv_bfloat16 s_p[2][2][64 * 40];   // [stage][hi/lo][64 i][40 pad(32 j)]
    __shared__ __nv_bfloat16 s_v[2][2][32 * 72];   // [stage][hi/lo][32 j][72 pad(64 d)]
    int bh = blockIdx.y, b = bh >> 4, h = bh & 15;
    int i0 = blockIdx.x << 6;
    int tid = threadIdx.x, lane = tid & 31, wid = tid >> 5;
    int wm = wid & 3, wn = wid >> 2;

    uint32_t sp[2][2], sv[2][2];
    #pragma unroll
    for (int st = 0; st < 2; st++) {
        #pragma unroll
        for (int t = 0; t < 2; t++) {
            sp[st][t] = smem_to_u32(&s_p[st][t][0]);
            sv[st][t] = smem_to_u32(&s_v[st][t][0]);
        }
    }

    const __nv_bfloat16* Ph = g_ph + ((size_t)bh * Nn + i0) * Nn;
    const __nv_bfloat16* Pl = g_pl + ((size_t)bh * Nn + i0) * Nn;
    const __nv_bfloat16* Vh = g_vh + (size_t)b * Nn * Dd + h * HDd;
    const __nv_bfloat16* Vl = g_vl + (size_t)b * Nn * Dd + h * HDd;

    // per-thread load slots: p rows 64 x 4 segs (16B) = 256 -> 1/thread per matrix
    int pr = tid >> 2, pg = tid & 3;
    // v rows 32 x 8 segs = 256 -> 1/thread per matrix
    int vr = tid >> 3, vg = tid & 7;

    float acc[4][4];
    #pragma unroll
    for (int i = 0; i < 4; i++)
        #pragma unroll
        for (int j = 0; j < 4; j++) acc[i][j] = 0.0f;

    // prefetch chunk 0
    cp16(sp[0][0] + (pr * 40 + pg * 8) * 2, Ph + (size_t)pr * Nn + pg * 8);
    cp16(sp[0][1] + (pr * 40 + pg * 8) * 2, Pl + (size_t)pr * Nn + pg * 8);
    cp16(sv[0][0] + (vr * 72 + vg * 8) * 2, Vh + (size_t)vr * Dd + vg * 8);
    cp16(sv[0][1] + (vr * 72 + vg * 8) * 2, Vl + (size_t)vr * Dd + vg * 8);
    CP_COMMIT();

    int rsel = lane & 15, csel = (lane >> 4) << 3;

    for (int c = 0; c < 32; c++) {
        int st = c & 1;
        if (c < 31) {
            int j1 = (c + 1) << 5, nst = st ^ 1;
            cp16(sp[nst][0] + (pr * 40 + pg * 8) * 2, Ph + (size_t)pr * Nn + j1 + pg * 8);
            cp16(sp[nst][1] + (pr * 40 + pg * 8) * 2, Pl + (size_t)pr * Nn + j1 + pg * 8);
            cp16(sv[nst][0] + (vr * 72 + vg * 8) * 2, Vh + (size_t)(j1 + vr) * Dd + vg * 8);
            cp16(sv[nst][1] + (vr * 72 + vg * 8) * 2, Vl + (size_t)(j1 + vr) * Dd + vg * 8);
            CP_COMMIT();
            CP_WAIT1();
        } else {
            CP_WAIT0();
        }
        __syncthreads();

        #pragma unroll
        for (int kk = 0; kk < 2; kk++) {
            uint32_t ah[4], al[4], vhf[2][4], vlf[2][4];
            int arow = wm * 16 + rsel;
            ldsm_x4(ah, sp[st][0] + (arow * 40 + kk * 16 + csel) * 2);
            ldsm_x4(al, sp[st][1] + (arow * 40 + kk * 16 + csel) * 2);
            #pragma unroll
            for (int db = 0; db < 2; db++) {
                int vcol = wn * 32 + db * 16 + csel;
                ldsm_x4_t(vhf[db], sv[st][0] + ((kk * 16 + rsel) * 72 + vcol) * 2);
                ldsm_x4_t(vlf[db], sv[st][1] + ((kk * 16 + rsel) * 72 + vcol) * 2);
            }
            #pragma unroll
            for (int db = 0; db < 2; db++) {
                mma_bf16(acc[2 * db + 0], ah, vhf[db][0], vhf[db][1]);
                mma_bf16(acc[2 * db + 1], ah, vhf[db][2], vhf[db][3]);
                mma_bf16(acc[2 * db + 0], al, vhf[db][0], vhf[db][1]);
                mma_bf16(acc[2 * db + 1], al, vhf[db][2], vhf[db][3]);
                mma_bf16(acc[2 * db + 0], ah, vlf[db][0], vlf[db][1]);
                mma_bf16(acc[2 * db + 1], ah, vlf[db][2], vlf[db][3]);
            }
        }
        __syncthreads();
    }

    // epilogue: AO hi/lo bf16 at [b][i][h*64 + d]
    #pragma unroll
    for (int nb = 0; nb < 4; nb++) {
        int i   = i0 + wm * 16 + (lane >> 2);
        int col = h * HDd + wn * 32 + nb * 8 + ((lane & 3) << 1);
        float l0, l1, l2, l3;
        __nv_bfloat162 h01 = split_hi2(acc[nb][0], acc[nb][1], &l0, &l1);
        __nv_bfloat162 h23 = split_hi2(acc[nb][2], acc[nb][3], &l2, &l3);
        size_t o0 = ((size_t)b * Nn + i) * Dd + col;
        size_t o1 = ((size_t)b * Nn + i + 8) * Dd + col;
        *(__nv_bfloat162*)(g_aoh + o0) = h01;
        *(__nv_bfloat162*)(g_aoh + o1) = h23;
        *(__nv_bfloat162*)(g_aol + o0) = __nv_bfloat162(__float2bfloat16_rn(l0), __float2bfloat16_rn(l1));
        *(__nv_bfloat162*)(g_aol + o1) = __nv_bfloat162(__float2bfloat16_rn(l2), __float2bfloat16_rn(l3));
    }
}

// ---------------- trajectory pairwise similarity ----------------
__global__ __launch_bounds__(1024) void traj_kernel(const float* __restrict__ pos,
                                                    const float* __restrict__ quat) {
    __shared__ float Pi[3][BT][32], Pj[3][BT][32];
    __shared__ float Qi[4][BT][32], Qj[4][BT][32];
    int i0 = blockIdx.y * 32, j0 = blockIdx.x * 32;
    int tid = threadIdx.y * 32 + threadIdx.x;

    for (int idx = tid; idx < BT * 32; idx += 1024) {
        int bt = idx >> 5, r = idx & 31;
        size_t pi = ((size_t)bt * Nn + i0 + r) * 3;
        size_t pj = ((size_t)bt * Nn + j0 + r) * 3;
        Pi[0][bt][r] = pos[pi + 0]; Pi[1][bt][r] = pos[pi + 1]; Pi[2][bt][r] = pos[pi + 2];
        Pj[0][bt][r] = pos[pj + 0]; Pj[1][bt][r] = pos[pj + 1]; Pj[2][bt][r] = pos[pj + 2];
        size_t qi = ((size_t)bt * Nn + i0 + r) * 4;
        size_t qj = ((size_t)bt * Nn + j0 + r) * 4;
        Qi[0][bt][r] = quat[qi + 0]; Qi[1][bt][r] = quat[qi + 1];
        Qi[2][bt][r] = quat[qi + 2]; Qi[3][bt][r] = quat[qi + 3];
        Qj[0][bt][r] = quat[qj + 0]; Qj[1][bt][r] = quat[qj + 1];
        Qj[2][bt][r] = quat[qj + 2]; Qj[3][bt][r] = quat[qj + 3];
    }
    __syncthreads();

    int ti = threadIdx.y, tj = threadIdx.x;
    float spd = 0.0f, sqm = 0.0f, sqp = 0.0f;
    #pragma unroll
    for (int bt = 0; bt < BT; bt++) {
        float dx = Pi[0][bt][ti] - Pj[0][bt][tj];
        float dy = Pi[1][bt][ti] - Pj[1][bt][tj];
        float dz = Pi[2][bt][ti] - Pj[2][bt][tj];
        spd += sqrtf(dx * dx + dy * dy + dz * dz);
        float a0 = Qi[0][bt][ti], a1 = Qi[1][bt][ti], a2 = Qi[2][bt][ti], a3 = Qi[3][bt][ti];
        float b0 = Qj[0][bt][tj], b1 = Qj[1][bt][tj], b2 = Qj[2][bt][tj], b3 = Qj[3][bt][tj];
        float m0 = a0 - b0, m1 = a1 - b1, m2 = a2 - b2, m3 = a3 - b3;
        float p0 = a0 + b0, p1 = a1 + b1, p2 = a2 + b2, p3 = a3 + b3;
        sqm += sqrtf(m0 * m0 + m1 * m1 + m2 * m2 + m3 * m3);
        sqp += sqrtf(p0 * p0 + p1 * p1 + p2 * p2 + p3 * p3);
    }
    float pd = spd * (1.0f / BT);
    float qd = fminf(sqm, sqp) * (1.0f / BT);
    g_traj[(size_t)(i0 + ti) * Nn + (j0 + tj)] = __expf(-(pd + qd));
}

// ---------------- row-normalize traj (folds in 0.5 bias scale) ----------------
__global__ __launch_bounds__(256) void traj_norm_kernel() {
    float* row = g_traj + (size_t)blockIdx.x * Nn;
    float4 v = ((const float4*)row)[threadIdx.x];
    float s = blk_sum(v.x + v.y + v.z + v.w);
    float sc = 0.5f / s;
    v.x *= sc; v.y *= sc; v.z *= sc; v.w *= sc;
    ((float4*)row)[threadIdx.x] = v;
}

// ---------------- launch ----------------
extern "C" void kernel_launch(void* const* d_in, const int* in_sizes, int n_in,
                              void* d_out, int out_size) {
    const float* data  = (const float*)d_in[0];
    const float* tpos  = (const float*)d_in[1];
    const float* tquat = (const float*)d_in[2];
    const float* cert  = (const float*)d_in[3];
    const float* Wq = (const float*)d_in[4];  const float* bq = (const float*)d_in[5];
    const float* Wk = (const float*)d_in[6];  const float* bk = (const float*)d_in[7];
    const float* Wv = (const float*)d_in[8];  const float* bv = (const float*)d_in[9];
    const float* Wo = (const float*)d_in[10]; const float* bo = (const float*)d_in[11];
    float* out = (float*)d_out;

    split_kernel<<<2048, 256>>>(data, 0, 524288);
    split_kernel<<<1024, 256>>>(Wq,   1, 262144);
    split_kernel<<<1024, 256>>>(Wk,   2, 262144);
    split_kernel<<<1024, 256>>>(Wv,   3, 262144);
    split_kernel<<<1024, 256>>>(Wo,   4, 262144);

    traj_kernel<<<dim3(32, 32), dim3(32, 32)>>>(tpos, tquat);
    traj_norm_kernel<<<Nn, 256>>>();

    qkv_tc<<<dim3(8, 16, 3), 256>>>(bq, bk, bv);
    scores_tc<<<dim3(16, 16, 32), 256>>>();
    softmax_kernel<<<Bb * Nn, 256>>>(cert, out + (size_t)Bb * Nn * Dd);
    pv_tc<<<dim3(16, 32), 256>>>();
    out_tc<<<dim3(8, 16), 256>>>(bo, out);
}

// round 6
// speedup vs baseline: 1.8245x; 1.1285x over previous
#include <cuda_runtime.h>
#include <cuda_bf16.h>
#include <math.h>
#include <stdint.h>

#define Bb  2
#define Tt  10
#define Nn  1024
#define Dd  1024
#define NHh 16
#define HDd 64
#define BT  (Bb*Tt)

// ---------------- scratch (static device globals; no allocation) ----------------
__device__ float g_traj[(size_t)Nn * Nn];

// bf16 hi/lo operand pairs
__device__ __nv_bfloat16 g_dh[(size_t)Bb * Nn * Dd],  g_dl[(size_t)Bb * Nn * Dd];
__device__ __nv_bfloat16 g_w3h[(size_t)3 * Dd * Dd],  g_w3l[(size_t)3 * Dd * Dd];
__device__ __nv_bfloat16 g_woh[(size_t)Dd * Dd],      g_wol[(size_t)Dd * Dd];
__device__ __nv_bfloat16 g_qh[(size_t)Bb * Nn * Dd],  g_ql[(size_t)Bb * Nn * Dd];   // Q/8
__device__ __nv_bfloat16 g_kh[(size_t)Bb * Nn * Dd],  g_kl[(size_t)Bb * Nn * Dd];
__device__ __nv_bfloat16 g_vh[(size_t)Bb * Nn * Dd],  g_vl[(size_t)Bb * Nn * Dd];
__device__ __nv_bfloat16 g_aoh[(size_t)Bb * Nn * Dd], g_aol[(size_t)Bb * Nn * Dd];
// unnormalized exp(scores) hi part (for entropy) + per-row 1/rowsum
__device__ __nv_bfloat16 g_eh[(size_t)Bb * NHh * Nn * Nn];
__device__ float g_invs[(size_t)Bb * NHh * Nn];

// ================= HMMA helpers =================
__device__ __forceinline__ uint32_t smem_to_u32(const void* p) {
    uint32_t a;
    asm("{ .reg .u64 t; cvta.to.shared.u64 t, %1; cvt.u32.u64 %0, t; }" : "=r"(a) : "l"(p));
    return a;
}
__device__ __forceinline__ void cp16(uint32_t dst, const void* src) {
    asm volatile("cp.async.cg.shared.global [%0], [%1], 16;" :: "r"(dst), "l"(src));
}
#define CP_COMMIT() asm volatile("cp.async.commit_group;" ::: "memory")
#define CP_WAIT1()  asm volatile("cp.async.wait_group 1;" ::: "memory")
#define CP_WAIT0()  asm volatile("cp.async.wait_group 0;" ::: "memory")

__device__ __forceinline__ void ldsm_x4(uint32_t* r, uint32_t addr) {
    asm volatile("ldmatrix.sync.aligned.m8n8.x4.shared.b16 {%0,%1,%2,%3}, [%4];"
                 : "=r"(r[0]), "=r"(r[1]), "=r"(r[2]), "=r"(r[3]) : "r"(addr));
}
__device__ __forceinline__ void ldsm_x4_t(uint32_t* r, uint32_t addr) {
    asm volatile("ldmatrix.sync.aligned.m8n8.x4.trans.shared.b16 {%0,%1,%2,%3}, [%4];"
                 : "=r"(r[0]), "=r"(r[1]), "=r"(r[2]), "=r"(r[3]) : "r"(addr));
}
__device__ __forceinline__ void mma_bf16(float* c, const uint32_t* a, uint32_t b0, uint32_t b1) {
    asm volatile(
        "mma.sync.aligned.m16n8k16.row.col.f32.bf16.bf16.f32 "
        "{%0,%1,%2,%3}, {%4,%5,%6,%7}, {%8,%9}, {%0,%1,%2,%3};"
        : "+f"(c[0]), "+f"(c[1]), "+f"(c[2]), "+f"(c[3])
        : "r"(a[0]), "r"(a[1]), "r"(a[2]), "r"(a[3]), "r"(b0), "r"(b1));
}
__device__ __forceinline__ __nv_bfloat162 split_hi2(float a, float b, float* ra, float* rb) {
    __nv_bfloat16 h0 = __float2bfloat16_rn(a), h1 = __float2bfloat16_rn(b);
    *ra = a - __bfloat162float(h0);
    *rb = b - __bfloat162float(h1);
    return __nv_bfloat162(h0, h1);
}
__device__ __forceinline__ uint32_t pack_bf162(__nv_bfloat16 a, __nv_bfloat16 b) {
    __nv_bfloat162 p(a, b);
    return *(uint32_t*)&p;
}

// ---------------- block reduction (256 threads) ----------------
__device__ __forceinline__ float blk_sum(float v) {
    __shared__ float red[8];
    #pragma unroll
    for (int o = 16; o > 0; o >>= 1) v += __shfl_xor_sync(0xffffffffu, v, o);
    int w = threadIdx.x >> 5, l = threadIdx.x & 31;
    if (l == 0) red[w] = v;
    __syncthreads();
    if (w == 0) {
        float r = (l < 8) ? red[l] : 0.0f;
        #pragma unroll
        for (int o = 4; o > 0; o >>= 1) r += __shfl_xor_sync(0xffffffffu, r, o);
        if (l == 0) red[0] = r;
    }
    __syncthreads();
    float out = red[0];
    __syncthreads();
    return out;
}

// ---------------- fp32 -> bf16 hi/lo splits ----------------
__global__ __launch_bounds__(256) void split_data(const float* __restrict__ s) {
    int i = blockIdx.x * 256 + threadIdx.x;          // 524288 float4s
    float4 x = ((const float4*)s)[i];
    float r0, r1, r2, r3;
    __nv_bfloat162 h01 = split_hi2(x.x, x.y, &r0, &r1);
    __nv_bfloat162 h23 = split_hi2(x.z, x.w, &r2, &r3);
    ((__nv_bfloat162*)g_dh)[i * 2 + 0] = h01;
    ((__nv_bfloat162*)g_dh)[i * 2 + 1] = h23;
    ((__nv_bfloat162*)g_dl)[i * 2 + 0] = __nv_bfloat162(__float2bfloat16_rn(r0), __float2bfloat16_rn(r1));
    ((__nv_bfloat162*)g_dl)[i * 2 + 1] = __nv_bfloat162(__float2bfloat16_rn(r2), __float2bfloat16_rn(r3));
}

__global__ __launch_bounds__(256) void split_w(const float* __restrict__ Wq, const float* __restrict__ Wk,
                                               const float* __restrict__ Wv, const float* __restrict__ Wo) {
    int blk = blockIdx.x;
    int m = blk >> 10;                                // 0..3
    const float* src = (m == 0) ? Wq : (m == 1) ? Wk : (m == 2) ? Wv : Wo;
    __nv_bfloat16* hi = (m < 3) ? g_w3h + (size_t)m * 1048576 : g_woh;
    __nv_bfloat16* lo = (m < 3) ? g_w3l + (size_t)m * 1048576 : g_wol;
    int i = (blk & 1023) * 256 + threadIdx.x;         // 262144 float4s per matrix
    float4 x = ((const float4*)src)[i];
    float r0, r1, r2, r3;
    __nv_bfloat162 h01 = split_hi2(x.x, x.y, &r0, &r1);
    __nv_bfloat162 h23 = split_hi2(x.z, x.w, &r2, &r3);
    ((__nv_bfloat162*)hi)[i * 2 + 0] = h01;
    ((__nv_bfloat162*)hi)[i * 2 + 1] = h23;
    ((__nv_bfloat162*)lo)[i * 2 + 0] = __nv_bfloat162(__float2bfloat16_rn(r0), __float2bfloat16_rn(r1));
    ((__nv_bfloat162*)lo)[i * 2 + 1] = __nv_bfloat162(__float2bfloat16_rn(r2), __float2bfloat16_rn(r3));
}

// ================= HMMA GEMM core (qkv / out projections) =================
__device__ __forceinline__ void hmma_gemm_body(const __nv_bfloat16* __restrict__ Ah,
                                               const __nv_bfloat16* __restrict__ Al,
                                               const __nv_bfloat16* __restrict__ Wh,
                                               const __nv_bfloat16* __restrict__ Wl,
                                               const float* __restrict__ bias,
                                               float scale, int mode,
                                               float* __restrict__ Cf,
                                               __nv_bfloat16* __restrict__ Chi,
                                               __nv_bfloat16* __restrict__ Clo) {
    __shared__ __nv_bfloat16 sbuf[2][4][128 * 24];
    int tid = threadIdx.x, lane = tid & 31, wid = tid >> 5;
    int wm = wid & 3, wn = wid >> 2;
    int m0 = blockIdx.y << 7, n0 = blockIdx.x << 7;

    const __nv_bfloat16* srcs[4] = {
        Ah + (size_t)m0 * Dd, Al + (size_t)m0 * Dd,
        Wh + (size_t)n0 * Dd, Wl + (size_t)n0 * Dd };

    uint32_t sb[2][4];
    #pragma unroll
    for (int st = 0; st < 2; st++)
        #pragma unroll
        for (int t = 0; t < 4; t++) sb[st][t] = smem_to_u32(&sbuf[st][t][0]);

    int lr = tid >> 1, lg = tid & 1;

    float acc[2][8][4];
    #pragma unroll
    for (int i = 0; i < 2; i++)
        #pragma unroll
        for (int j = 0; j < 8; j++)
            #pragma unroll
            for (int k = 0; k < 4; k++) acc[i][j][k] = 0.0f;

    #pragma unroll
    for (int t = 0; t < 4; t++)
        cp16(sb[0][t] + lr * 48 + lg * 16, srcs[t] + (size_t)lr * Dd + lg * 8);
    CP_COMMIT();

    int rsel = lane & 15;
    int csel = (lane >> 4) << 3;

    for (int c = 0; c < 64; c++) {
        int st = c & 1;
        if (c < 63) {
            int kc = (c + 1) << 4, nst = st ^ 1;
            #pragma unroll
            for (int t = 0; t < 4; t++)
                cp16(sb[nst][t] + lr * 48 + lg * 16, srcs[t] + (size_t)lr * Dd + kc + lg * 8);
            CP_COMMIT();
            CP_WAIT1();
        } else {
            CP_WAIT0();
        }
        __syncthreads();

        uint32_t ah[2][4], al[2][4], bh[4][4], bl[4][4];
        #pragma unroll
        for (int mb = 0; mb < 2; mb++) {
            int row = wm * 32 + mb * 16 + rsel;
            ldsm_x4(ah[mb], sb[st][0] + (row * 24 + csel) * 2);
            ldsm_x4(al[mb], sb[st][1] + (row * 24 + csel) * 2);
        }
        #pragma unroll
        for (int np = 0; np < 4; np++) {
            int row = wn * 64 + np * 16 + rsel;
            ldsm_x4(bh[np], sb[st][2] + (row * 24 + csel) * 2);
            ldsm_x4(bl[np], sb[st][3] + (row * 24 + csel) * 2);
        }
        #pragma unroll
        for (int mb = 0; mb < 2; mb++) {
            #pragma unroll
            for (int np = 0; np < 4; np++) {
                mma_bf16(acc[mb][2 * np + 0], ah[mb], bh[np][0], bh[np][2]);
                mma_bf16(acc[mb][2 * np + 1], ah[mb], bh[np][1], bh[np][3]);
                mma_bf16(acc[mb][2 * np + 0], ah[mb], bl[np][0], bl[np][2]);
                mma_bf16(acc[mb][2 * np + 1], ah[mb], bl[np][1], bl[np][3]);
                mma_bf16(acc[mb][2 * np + 0], al[mb], bh[np][0], bh[np][2]);
                mma_bf16(acc[mb][2 * np + 1], al[mb], bh[np][1], bh[np][3]);
            }
        }
        __syncthreads();
    }

    #pragma unroll
    for (int mb = 0; mb < 2; mb++) {
        int r0 = m0 + wm * 32 + mb * 16 + (lane >> 2);
        #pragma unroll
        for (int nb = 0; nb < 8; nb++) {
            int col = n0 + wn * 64 + nb * 8 + ((lane & 3) << 1);
            float b0 = bias[col], b1 = bias[col + 1];
            float x0 = (acc[mb][nb][0] + b0) * scale, x1 = (acc[mb][nb][1] + b1) * scale;
            float x2 = (acc[mb][nb][2] + b0) * scale, x3 = (acc[mb][nb][3] + b1) * scale;
            if (mode == 1) {
                *(float2*)(Cf + (size_t)r0 * Dd + col)       = make_float2(x0, x1);
                *(float2*)(Cf + (size_t)(r0 + 8) * Dd + col) = make_float2(x2, x3);
            } else {
                float l0, l1, l2, l3;
                __nv_bfloat162 h01 = split_hi2(x0, x1, &l0, &l1);
                __nv_bfloat162 h23 = split_hi2(x2, x3, &l2, &l3);
                *(__nv_bfloat162*)(Chi + (size_t)r0 * Dd + col)       = h01;
                *(__nv_bfloat162*)(Chi + (size_t)(r0 + 8) * Dd + col) = h23;
                *(__nv_bfloat162*)(Clo + (size_t)r0 * Dd + col) =
                    __nv_bfloat162(__float2bfloat16_rn(l0), __float2bfloat16_rn(l1));
                *(__nv_bfloat162*)(Clo + (size_t)(r0 + 8) * Dd + col) =
                    __nv_bfloat162(__float2bfloat16_rn(l2), __float2bfloat16_rn(l3));
            }
        }
    }
}

__global__ __launch_bounds__(256, 1) void qkv_tc(const float* __restrict__ bq,
                                                 const float* __restrict__ bk,
                                                 const float* __restrict__ bv) {
    int z = blockIdx.z;
    const __nv_bfloat16* Wh = g_w3h + (size_t)z * 1048576;
    const __nv_bfloat16* Wl = g_w3l + (size_t)z * 1048576;
    const float* bias = (z == 0) ? bq : (z == 1) ? bk : bv;
    __nv_bfloat16* Chi = (z == 0) ? g_qh : (z == 1) ? g_kh : g_vh;
    __nv_bfloat16* Clo = (z == 0) ? g_ql : (z == 1) ? g_kl : g_vl;
    float scale = (z == 0) ? 0.125f : 1.0f;
    hmma_gemm_body(g_dh, g_dl, Wh, Wl, bias, scale, 0, nullptr, Chi, Clo);
}

__global__ __launch_bounds__(256, 1) void out_tc(const float* __restrict__ bo,
                                                 float* __restrict__ out) {
    hmma_gemm_body(g_aoh, g_aol, g_woh, g_wol, bo, 1.0f, 1, out, nullptr, nullptr);
}

// ================= fused attention: scores+traj -> exp -> PV, flash-style =================
// grid (16 i-tiles, 32 bh). CTA: 64 i-rows, loops 32 j-chunks of 32.
// 8 warps: wm=wid&3 (16 i rows), wn=wid>>2 (16 j cols per chunk).
// e stays in registers (C-frag -> A-frag repack); normalization deferred (1/rowsum in epilogue).
// Writes: e_hi (bf16, for entropy), invs, AO hi/lo.
#define OQH 0
#define OQL 9216
#define OKH 18432
#define OKL 23040
#define OVH 27648
#define OVL 32256
#define ORS 36864
#define OIV 37376

__global__ __launch_bounds__(256, 1) void attn_fused() {
    __shared__ __align__(16) char sm[37632];
    uint32_t ub = smem_to_u32(sm);
    int tid = threadIdx.x, lane = tid & 31, wid = tid >> 5;
    int wm = wid & 3, wn = wid >> 2;
    int g = lane >> 2, t = lane & 3;
    int rsel = lane & 15, csel = (lane >> 4) << 3;
    int bh = blockIdx.y, b = bh >> 4, h = bh & 15;
    int i0 = blockIdx.x << 6;

    // ---- prologue: Q (64x64 hi/lo) + K/V chunk 0 via cp.async ----
    #pragma unroll
    for (int s = 0; s < 4; s++) {                       // Q: 2 mats x 64 rows x 8 segs
        int idx = tid + (s << 8);
        int mat = idx >> 9, row = (idx >> 3) & 63, seg = idx & 7;
        const __nv_bfloat16* src = (mat == 0 ? g_qh : g_ql) +
            ((size_t)(b * Nn + i0 + row)) * Dd + h * HDd + seg * 8;
        cp16(ub + (mat ? OQL : OQH) + (row * 72 + seg * 8) * 2, src);
    }
    const __nv_bfloat16* kvsrc[4] = { g_kh, g_kl, g_vh, g_vl };
    #pragma unroll
    for (int s = 0; s < 4; s++) {                       // K/V chunk0: 4 mats x 32 rows x 8 segs
        int idx = tid + (s << 8);
        int mat = idx >> 8, row = (idx >> 3) & 31, seg = idx & 7;
        const __nv_bfloat16* src = kvsrc[mat] + ((size_t)(b * Nn + row)) * Dd + h * HDd + seg * 8;
        cp16(ub + OKH + mat * 4608 + (row * 72 + seg * 8) * 2, src);
    }
    CP_COMMIT();
    CP_WAIT0();
    __syncthreads();

    float pacc[8][4];
    #pragma unroll
    for (int i = 0; i < 8; i++)
        #pragma unroll
        for (int j = 0; j < 4; j++) pacc[i][j] = 0.0f;
    float rs0 = 0.0f, rs1 = 0.0f;

    int i_r0 = i0 + wm * 16 + g;

    for (int c = 0; c < 32; c++) {
        // stage next chunk into registers (latency hidden by compute below)
        float4 stage[4];
        int smat[4], srow[4], sseg[4];
        if (c < 31) {
            int jc1 = (c + 1) << 5;
            #pragma unroll
            for (int s = 0; s < 4; s++) {
                int idx = tid + (s << 8);
                smat[s] = idx >> 8; srow[s] = (idx >> 3) & 31; sseg[s] = idx & 7;
                stage[s] = *(const float4*)(kvsrc[smat[s]] +
                    ((size_t)(b * Nn + jc1 + srow[s])) * Dd + h * HDd + sseg[s] * 8);
            }
        }

        int jc = c << 5;
        // ---- scores: 16i x 16j per warp, 3-pass hi/lo ----
        float sacc0[4] = {0.f, 0.f, 0.f, 0.f};
        float sacc1[4] = {0.f, 0.f, 0.f, 0.f};
        #pragma unroll
        for (int k = 0; k < 4; k++) {
            uint32_t qh[4], ql[4], kh[4], kl[4];
            uint32_t qaddr = (uint32_t)(((wm * 16 + rsel) * 72 + k * 16 + csel) * 2);
            uint32_t kaddr = (uint32_t)(((wn * 16 + rsel) * 72 + k * 16 + csel) * 2);
            ldsm_x4(qh, ub + OQH + qaddr);
            ldsm_x4(ql, ub + OQL + qaddr);
            ldsm_x4(kh, ub + OKH + kaddr);
            ldsm_x4(kl, ub + OKL + kaddr);
            mma_bf16(sacc0, qh, kh[0], kh[2]); mma_bf16(sacc1, qh, kh[1], kh[3]);
            mma_bf16(sacc0, qh, kl[0], kl[2]); mma_bf16(sacc1, qh, kl[1], kl[3]);
            mma_bf16(sacc0, ql, kh[0], kh[2]); mma_bf16(sacc1, ql, kh[1], kh[3]);
        }

        // ---- traj bias + exp + split + e_hi store + rowsums ----
        uint32_t ah[4], al[4];
        {
            float* sa = sacc0;
            #pragma unroll
            for (int nt = 0; nt < 2; nt++) {
                int jj = jc + wn * 16 + nt * 8 + 2 * t;
                float2 tv0 = *(const float2*)(g_traj + (size_t)i_r0 * Nn + jj);
                float2 tv1 = *(const float2*)(g_traj + (size_t)(i_r0 + 8) * Nn + jj);
                float e0 = __expf(sa[0] + tv0.x), e1 = __expf(sa[1] + tv0.y);
                float e2 = __expf(sa[2] + tv1.x), e3 = __expf(sa[3] + tv1.y);
                rs0 += e0 + e1; rs1 += e2 + e3;
                __nv_bfloat16 h0 = __float2bfloat16_rn(e0), h1 = __float2bfloat16_rn(e1);
                __nv_bfloat16 h2 = __float2bfloat16_rn(e2), h3 = __float2bfloat16_rn(e3);
                float l0 = e0 - __bfloat162float(h0), l1 = e1 - __bfloat162float(h1);
                float l2 = e2 - __bfloat162float(h2), l3 = e3 - __bfloat162float(h3);
                *(__nv_bfloat162*)(g_eh + ((size_t)bh * Nn + i_r0) * Nn + jj)     = __nv_bfloat162(h0, h1);
                *(__nv_bfloat162*)(g_eh + ((size_t)bh * Nn + i_r0 + 8) * Nn + jj) = __nv_bfloat162(h2, h3);
                ah[nt * 2 + 0] = pack_bf162(h0, h1);
                ah[nt * 2 + 1] = pack_bf162(h2, h3);
                al[nt * 2 + 0] = pack_bf162(__float2bfloat16_rn(l0), __float2bfloat16_rn(l1));
                al[nt * 2 + 1] = pack_bf162(__float2bfloat16_rn(l2), __float2bfloat16_rn(l3));
                sa = sacc1;
            }
        }

        // ---- PV: AO(16i x 64d) += e(16x16) · V(16x64), 3-pass ----
        #pragma unroll
        for (int db = 0; db < 4; db++) {
            uint32_t vh[4], vl[4];
            uint32_t vaddr = (uint32_t)(((wn * 16 + rsel) * 72 + db * 16 + csel) * 2);
            ldsm_x4_t(vh, ub + OVH + vaddr);
            ldsm_x4_t(vl, ub + OVL + vaddr);
            mma_bf16(pacc[2 * db + 0], ah, vh[0], vh[1]); mma_bf16(pacc[2 * db + 1], ah, vh[2], vh[3]);
            mma_bf16(pacc[2 * db + 0], al, vh[0], vh[1]); mma_bf16(pacc[2 * db + 1], al, vh[2], vh[3]);
            mma_bf16(pacc[2 * db + 0], ah, vl[0], vl[1]); mma_bf16(pacc[2 * db + 1], ah, vl[2], vl[3]);
        }

        __syncthreads();
        if (c < 31) {
            #pragma unroll
            for (int s = 0; s < 4; s++)
                *(float4*)(sm + OKH + smat[s] * 4608 + (srow[s] * 72 + sseg[s] * 8) * 2) = stage[s];
        }
        __syncthreads();
    }

    // ---- rowsum reduce -> invs ----
    rs0 += __shfl_xor_sync(0xffffffffu, rs0, 1);
    rs0 += __shfl_xor_sync(0xffffffffu, rs0, 2);
    rs1 += __shfl_xor_sync(0xffffffffu, rs1, 1);
    rs1 += __shfl_xor_sync(0xffffffffu, rs1, 2);
    float* s_rs = (float*)(sm + ORS);
    float* s_iv = (float*)(sm + OIV);
    if (t == 0) {
        s_rs[wn * 64 + wm * 16 + g]     = rs0;
        s_rs[wn * 64 + wm * 16 + g + 8] = rs1;
    }
    __syncthreads();
    if (tid < 64) {
        float s = s_rs[tid] + s_rs[64 + tid];
        float inv = 1.0f / s;
        s_iv[tid] = inv;
        g_invs[(size_t)bh * Nn + i0 + tid] = inv;
    }
    __syncthreads();

    // ---- AO cross-warp (wn) reduce, scale by invs, write hi/lo ----
    float* red = (float*)(sm + OKH) + wm * 1056;   // [16][66] per wm group
    if (wn == 0) {
        #pragma unroll
        for (int nt = 0; nt < 8; nt++) {
            int col = nt * 8 + 2 * t;
            red[g * 66 + col]           = pacc[nt][0];
            red[g * 66 + col + 1]       = pacc[nt][1];
            red[(g + 8) * 66 + col]     = pacc[nt][2];
            red[(g + 8) * 66 + col + 1] = pacc[nt][3];
        }
    }
    __syncthreads();
    if (wn == 1) {
        float inv0 = s_iv[wm * 16 + g], inv1 = s_iv[wm * 16 + g + 8];
        #pragma unroll
        for (int nt = 0; nt < 8; nt++) {
            int col = nt * 8 + 2 * t;
            float x0 = (pacc[nt][0] + red[g * 66 + col])           * inv0;
            float x1 = (pacc[nt][1] + red[g * 66 + col + 1])       * inv0;
            float x2 = (pacc[nt][2] + red[(g + 8) * 66 + col])     * inv1;
            float x3 = (pacc[nt][3] + red[(g + 8) * 66 + col + 1]) * inv1;
            float l0, l1, l2, l3;
            __nv_bfloat162 h01 = split_hi2(x0, x1, &l0, &l1);
            __nv_bfloat162 h23 = split_hi2(x2, x3, &l2, &l3);
            size_t o0 = ((size_t)b * Nn + i_r0) * Dd + h * HDd + col;
            size_t o1 = ((size_t)b * Nn + i_r0 + 8) * Dd + h * HDd + col;
            *(__nv_bfloat162*)(g_aoh + o0) = h01;
            *(__nv_bfloat162*)(g_aoh + o1) = h23;
            *(__nv_bfloat162*)(g_aol + o0) = __nv_bfloat162(__float2bfloat16_rn(l0), __float2bfloat16_rn(l1));
            *(__nv_bfloat162*)(g_aol + o1) = __nv_bfloat162(__float2bfloat16_rn(l2), __float2bfloat16_rn(l3));
        }
    }
}

// ---------------- entropy + certainty from e_hi and invs ----------------
__global__ __launch_bounds__(256) void entropy_kernel(const float* __restrict__ cert,
                                                      float* __restrict__ out_cert) {
    int bi = blockIdx.x;
    int b = bi >> 10, i = bi & 1023;
    int tid = threadIdx.x;

    float a0 = 0.f, a1 = 0.f, a2 = 0.f, a3 = 0.f;
    #pragma unroll
    for (int hh = 0; hh < NHh; hh++) {
        int bh = b * NHh + hh;
        float inv = g_invs[(size_t)bh * Nn + i];
        const __nv_bfloat162* row = (const __nv_bfloat162*)(g_eh + ((size_t)bh * Nn + i) * Nn);
        __nv_bfloat162 v0 = row[tid * 2], v1 = row[tid * 2 + 1];
        a0 += __bfloat162float(v0.x) * inv;
        a1 += __bfloat162float(v0.y) * inv;
        a2 += __bfloat162float(v1.x) * inv;
        a3 += __bfloat162float(v1.y) * inv;
    }
    a0 *= (1.0f / NHh); a1 *= (1.0f / NHh); a2 *= (1.0f / NHh); a3 *= (1.0f / NHh);
    float hl = 0.0f;
    a0 = fmaxf(a0, 1e-10f); hl -= a0 * __logf(a0);
    a1 = fmaxf(a1, 1e-10f); hl -= a1 * __logf(a1);
    a2 = fmaxf(a2, 1e-10f); hl -= a2 * __logf(a2);
    a3 = fmaxf(a3, 1e-10f); hl -= a3 * __logf(a3);
    float H = blk_sum(hl);
    if (tid == 0) {
        float sig = 1.0f / (1.0f + __expf(H - 6.9314718055994531f));   // Hmax = ln(1024)
        out_cert[bi] = fmaxf(cert[bi], sig);
    }
}

// ---------------- trajectory pairwise similarity ----------------
__device__ __forceinline__ float fast_sqrt(float x) {
    return x * rsqrtf(x + 1e-30f);
}

__global__ __launch_bounds__(1024) void traj_kernel(const float* __restrict__ pos,
                                                    const float* __restrict__ quat) {
    __shared__ float Pi[3][BT][32], Pj[3][BT][32];
    __shared__ float Qi[4][BT][32], Qj[4][BT][32];
    int i0 = blockIdx.y * 32, j0 = blockIdx.x * 32;
    int tid = threadIdx.y * 32 + threadIdx.x;

    for (int idx = tid; idx < BT * 32; idx += 1024) {
        int bt = idx >> 5, r = idx & 31;
        size_t pi = ((size_t)bt * Nn + i0 + r) * 3;
        size_t pj = ((size_t)bt * Nn + j0 + r) * 3;
        Pi[0][bt][r] = pos[pi + 0]; Pi[1][bt][r] = pos[pi + 1]; Pi[2][bt][r] = pos[pi + 2];
        Pj[0][bt][r] = pos[pj + 0]; Pj[1][bt][r] = pos[pj + 1]; Pj[2][bt][r] = pos[pj + 2];
        size_t qi = ((size_t)bt * Nn + i0 + r) * 4;
        size_t qj = ((size_t)bt * Nn + j0 + r) * 4;
        Qi[0][bt][r] = quat[qi + 0]; Qi[1][bt][r] = quat[qi + 1];
        Qi[2][bt][r] = quat[qi + 2]; Qi[3][bt][r] = quat[qi + 3];
        Qj[0][bt][r] = quat[qj + 0]; Qj[1][bt][r] = quat[qj + 1];
        Qj[2][bt][r] = quat[qj + 2]; Qj[3][bt][r] = quat[qj + 3];
    }
    __syncthreads();

    int ti = threadIdx.y, tj = threadIdx.x;
    float spd = 0.0f, sqm = 0.0f, sqp = 0.0f;
    #pragma unroll
    for (int bt = 0; bt < BT; bt++) {
        float dx = Pi[0][bt][ti] - Pj[0][bt][tj];
        float dy = Pi[1][bt][ti] - Pj[1][bt][tj];
        float dz = Pi[2][bt][ti] - Pj[2][bt][tj];
        spd += fast_sqrt(dx * dx + dy * dy + dz * dz);
        float a0 = Qi[0][bt][ti], a1 = Qi[1][bt][ti], a2 = Qi[2][bt][ti], a3 = Qi[3][bt][ti];
        float b0 = Qj[0][bt][tj], b1 = Qj[1][bt][tj], b2 = Qj[2][bt][tj], b3 = Qj[3][bt][tj];
        float m0 = a0 - b0, m1 = a1 - b1, m2 = a2 - b2, m3 = a3 - b3;
        float p0 = a0 + b0, p1 = a1 + b1, p2 = a2 + b2, p3 = a3 + b3;
        sqm += fast_sqrt(m0 * m0 + m1 * m1 + m2 * m2 + m3 * m3);
        sqp += fast_sqrt(p0 * p0 + p1 * p1 + p2 * p2 + p3 * p3);
    }
    float pd = spd * (1.0f / BT);
    float qd = fminf(sqm, sqp) * (1.0f / BT);
    g_traj[(size_t)(i0 + ti) * Nn + (j0 + tj)] = __expf(-(pd + qd));
}

// ---------------- row-normalize traj (folds in 0.5 bias scale) ----------------
__global__ __launch_bounds__(256) void traj_norm_kernel() {
    float* row = g_traj + (size_t)blockIdx.x * Nn;
    float4 v = ((const float4*)row)[threadIdx.x];
    float s = blk_sum(v.x + v.y + v.z + v.w);
    float sc = 0.5f / s;
    v.x *= sc; v.y *= sc; v.z *= sc; v.w *= sc;
    ((float4*)row)[threadIdx.x] = v;
}

// ---------------- launch ----------------
extern "C" void kernel_launch(void* const* d_in, const int* in_sizes, int n_in,
                              void* d_out, int out_size) {
    const float* data  = (const float*)d_in[0];
    const float* tpos  = (const float*)d_in[1];
    const float* tquat = (const float*)d_in[2];
    const float* cert  = (const float*)d_in[3];
    const float* Wq = (const float*)d_in[4];  const float* bq = (const float*)d_in[5];
    const float* Wk = (const float*)d_in[6];  const float* bk = (const float*)d_in[7];
    const float* Wv = (const float*)d_in[8];  const float* bv = (const float*)d_in[9];
    const float* Wo = (const float*)d_in[10]; const float* bo = (const float*)d_in[11];
    float* out = (float*)d_out;

    split_data<<<2048, 256>>>(data);                    // 1
    split_w<<<4096, 256>>>(Wq, Wk, Wv, Wo);             // 2
    traj_kernel<<<dim3(32, 32), dim3(32, 32)>>>(tpos, tquat);  // 3
    traj_norm_kernel<<<Nn, 256>>>();                    // 4
    qkv_tc<<<dim3(8, 16, 3), 256>>>(bq, bk, bv);        // 5
    attn_fused<<<dim3(16, 32), 256>>>();                // 6  <- ncu captures this
    entropy_kernel<<<Bb * Nn, 256>>>(cert, out + (size_t)Bb * Nn * Dd);  // 7
    out_tc<<<dim3(8, 16), 256>>>(bo, out);              // 8
}

// round 7
// speedup vs baseline: 2.0750x; 1.1373x over previous
#include <cuda_runtime.h>
#include <cuda_bf16.h>
#include <math.h>
#include <stdint.h>

#define Bb  2
#define Tt  10
#define Nn  1024
#define Dd  1024
#define NHh 16
#define HDd 64
#define BT  (Bb*Tt)

// ---------------- scratch (static device globals; no allocation) ----------------
__device__ float g_traj[(size_t)Nn * Nn];

// bf16 hi/lo operand pairs
__device__ __nv_bfloat16 g_dh[(size_t)Bb * Nn * Dd],  g_dl[(size_t)Bb * Nn * Dd];
__device__ __nv_bfloat16 g_w3h[(size_t)3 * Dd * Dd],  g_w3l[(size_t)3 * Dd * Dd];
__device__ __nv_bfloat16 g_woh[(size_t)Dd * Dd],      g_wol[(size_t)Dd * Dd];
__device__ __nv_bfloat16 g_qh[(size_t)Bb * Nn * Dd],  g_ql[(size_t)Bb * Nn * Dd];   // Q/8
__device__ __nv_bfloat16 g_kh[(size_t)Bb * Nn * Dd],  g_kl[(size_t)Bb * Nn * Dd];
__device__ __nv_bfloat16 g_vh[(size_t)Bb * Nn * Dd],  g_vl[(size_t)Bb * Nn * Dd];
__device__ __nv_bfloat16 g_aoh[(size_t)Bb * Nn * Dd], g_aol[(size_t)Bb * Nn * Dd];
// unnormalized exp(scores) hi part (for entropy) + per-row 1/rowsum
__device__ __nv_bfloat16 g_eh[(size_t)Bb * NHh * Nn * Nn];
__device__ float g_invs[(size_t)Bb * NHh * Nn];

// ================= HMMA helpers =================
__device__ __forceinline__ uint32_t smem_to_u32(const void* p) {
    uint32_t a;
    asm("{ .reg .u64 t; cvta.to.shared.u64 t, %1; cvt.u32.u64 %0, t; }" : "=r"(a) : "l"(p));
    return a;
}
__device__ __forceinline__ void cp16(uint32_t dst, const void* src) {
    asm volatile("cp.async.cg.shared.global [%0], [%1], 16;" :: "r"(dst), "l"(src));
}
#define CP_COMMIT() asm volatile("cp.async.commit_group;" ::: "memory")
#define CP_WAIT1()  asm volatile("cp.async.wait_group 1;" ::: "memory")
#define CP_WAIT0()  asm volatile("cp.async.wait_group 0;" ::: "memory")

__device__ __forceinline__ void ldsm_x4(uint32_t* r, uint32_t addr) {
    asm volatile("ldmatrix.sync.aligned.m8n8.x4.shared.b16 {%0,%1,%2,%3}, [%4];"
                 : "=r"(r[0]), "=r"(r[1]), "=r"(r[2]), "=r"(r[3]) : "r"(addr));
}
__device__ __forceinline__ void ldsm_x4_t(uint32_t* r, uint32_t addr) {
    asm volatile("ldmatrix.sync.aligned.m8n8.x4.trans.shared.b16 {%0,%1,%2,%3}, [%4];"
                 : "=r"(r[0]), "=r"(r[1]), "=r"(r[2]), "=r"(r[3]) : "r"(addr));
}
__device__ __forceinline__ void mma_bf16(float* c, const uint32_t* a, uint32_t b0, uint32_t b1) {
    asm volatile(
        "mma.sync.aligned.m16n8k16.row.col.f32.bf16.bf16.f32 "
        "{%0,%1,%2,%3}, {%4,%5,%6,%7}, {%8,%9}, {%0,%1,%2,%3};"
        : "+f"(c[0]), "+f"(c[1]), "+f"(c[2]), "+f"(c[3])
        : "r"(a[0]), "r"(a[1]), "r"(a[2]), "r"(a[3]), "r"(b0), "r"(b1));
}
__device__ __forceinline__ __nv_bfloat162 split_hi2(float a, float b, float* ra, float* rb) {
    __nv_bfloat16 h0 = __float2bfloat16_rn(a), h1 = __float2bfloat16_rn(b);
    *ra = a - __bfloat162float(h0);
    *rb = b - __bfloat162float(h1);
    return __nv_bfloat162(h0, h1);
}
__device__ __forceinline__ uint32_t pack_bf162(__nv_bfloat16 a, __nv_bfloat16 b) {
    __nv_bfloat162 p(a, b);
    return *(uint32_t*)&p;
}

// ---------------- block reduction (256 threads) ----------------
__device__ __forceinline__ float blk_sum(float v) {
    __shared__ float red[8];
    #pragma unroll
    for (int o = 16; o > 0; o >>= 1) v += __shfl_xor_sync(0xffffffffu, v, o);
    int w = threadIdx.x >> 5, l = threadIdx.x & 31;
    if (l == 0) red[w] = v;
    __syncthreads();
    if (w == 0) {
        float r = (l < 8) ? red[l] : 0.0f;
        #pragma unroll
        for (int o = 4; o > 0; o >>= 1) r += __shfl_xor_sync(0xffffffffu, r, o);
        if (l == 0) red[0] = r;
    }
    __syncthreads();
    float out = red[0];
    __syncthreads();
    return out;
}

// ---------------- fp32 -> bf16 hi/lo splits ----------------
__global__ __launch_bounds__(256) void split_data(const float* __restrict__ s) {
    int i = blockIdx.x * 256 + threadIdx.x;
    float4 x = ((const float4*)s)[i];
    float r0, r1, r2, r3;
    __nv_bfloat162 h01 = split_hi2(x.x, x.y, &r0, &r1);
    __nv_bfloat162 h23 = split_hi2(x.z, x.w, &r2, &r3);
    ((__nv_bfloat162*)g_dh)[i * 2 + 0] = h01;
    ((__nv_bfloat162*)g_dh)[i * 2 + 1] = h23;
    ((__nv_bfloat162*)g_dl)[i * 2 + 0] = __nv_bfloat162(__float2bfloat16_rn(r0), __float2bfloat16_rn(r1));
    ((__nv_bfloat162*)g_dl)[i * 2 + 1] = __nv_bfloat162(__float2bfloat16_rn(r2), __float2bfloat16_rn(r3));
}

__global__ __launch_bounds__(256) void split_w(const float* __restrict__ Wq, const float* __restrict__ Wk,
                                               const float* __restrict__ Wv, const float* __restrict__ Wo) {
    int blk = blockIdx.x;
    int m = blk >> 10;
    const float* src = (m == 0) ? Wq : (m == 1) ? Wk : (m == 2) ? Wv : Wo;
    __nv_bfloat16* hi = (m < 3) ? g_w3h + (size_t)m * 1048576 : g_woh;
    __nv_bfloat16* lo = (m < 3) ? g_w3l + (size_t)m * 1048576 : g_wol;
    int i = (blk & 1023) * 256 + threadIdx.x;
    float4 x = ((const float4*)src)[i];
    float r0, r1, r2, r3;
    __nv_bfloat162 h01 = split_hi2(x.x, x.y, &r0, &r1);
    __nv_bfloat162 h23 = split_hi2(x.z, x.w, &r2, &r3);
    ((__nv_bfloat162*)hi)[i * 2 + 0] = h01;
    ((__nv_bfloat162*)hi)[i * 2 + 1] = h23;
    ((__nv_bfloat162*)lo)[i * 2 + 0] = __nv_bfloat162(__float2bfloat16_rn(r0), __float2bfloat16_rn(r1));
    ((__nv_bfloat162*)lo)[i * 2 + 1] = __nv_bfloat162(__float2bfloat16_rn(r2), __float2bfloat16_rn(r3));
}

// ================= HMMA GEMM core (qkv / out projections) =================
// 128x128 CTA tile, 8 warps (4m x 2n), K-chunk 16, cp.async double buffer, 48KB smem,
// 2 CTAs/SM (regs capped at 128; B frags interleaved into np-loop to avoid spills).
__device__ __forceinline__ void hmma_gemm_body(const __nv_bfloat16* __restrict__ Ah,
                                               const __nv_bfloat16* __restrict__ Al,
                                               const __nv_bfloat16* __restrict__ Wh,
                                               const __nv_bfloat16* __restrict__ Wl,
                                               const float* __restrict__ bias,
                                               float scale, int mode,
                                               float* __restrict__ Cf,
                                               __nv_bfloat16* __restrict__ Chi,
                                               __nv_bfloat16* __restrict__ Clo) {
    __shared__ __nv_bfloat16 sbuf[2][4][128 * 24];
    int tid = threadIdx.x, lane = tid & 31, wid = tid >> 5;
    int wm = wid & 3, wn = wid >> 2;
    int m0 = blockIdx.y << 7, n0 = blockIdx.x << 7;

    const __nv_bfloat16* srcs[4] = {
        Ah + (size_t)m0 * Dd, Al + (size_t)m0 * Dd,
        Wh + (size_t)n0 * Dd, Wl + (size_t)n0 * Dd };

    uint32_t sb[2][4];
    #pragma unroll
    for (int st = 0; st < 2; st++)
        #pragma unroll
        for (int t = 0; t < 4; t++) sb[st][t] = smem_to_u32(&sbuf[st][t][0]);

    int lr = tid >> 1, lg = tid & 1;

    float acc[2][8][4];
    #pragma unroll
    for (int i = 0; i < 2; i++)
        #pragma unroll
        for (int j = 0; j < 8; j++)
            #pragma unroll
            for (int k = 0; k < 4; k++) acc[i][j][k] = 0.0f;

    #pragma unroll
    for (int t = 0; t < 4; t++)
        cp16(sb[0][t] + lr * 48 + lg * 16, srcs[t] + (size_t)lr * Dd + lg * 8);
    CP_COMMIT();

    int rsel = lane & 15;
    int csel = (lane >> 4) << 3;

    for (int c = 0; c < 64; c++) {
        int st = c & 1;
        if (c < 63) {
            int kc = (c + 1) << 4, nst = st ^ 1;
            #pragma unroll
            for (int t = 0; t < 4; t++)
                cp16(sb[nst][t] + lr * 48 + lg * 16, srcs[t] + (size_t)lr * Dd + kc + lg * 8);
            CP_COMMIT();
            CP_WAIT1();
        } else {
            CP_WAIT0();
        }
        __syncthreads();

        uint32_t ah[2][4], al[2][4];
        #pragma unroll
        for (int mb = 0; mb < 2; mb++) {
            int row = wm * 32 + mb * 16 + rsel;
            ldsm_x4(ah[mb], sb[st][0] + (row * 24 + csel) * 2);
            ldsm_x4(al[mb], sb[st][1] + (row * 24 + csel) * 2);
        }
        #pragma unroll
        for (int np = 0; np < 4; np++) {
            uint32_t bh[4], bl[4];
            int row = wn * 64 + np * 16 + rsel;
            ldsm_x4(bh, sb[st][2] + (row * 24 + csel) * 2);
            ldsm_x4(bl, sb[st][3] + (row * 24 + csel) * 2);
            #pragma unroll
            for (int mb = 0; mb < 2; mb++) {
                mma_bf16(acc[mb][2 * np + 0], ah[mb], bh[0], bh[2]);
                mma_bf16(acc[mb][2 * np + 1], ah[mb], bh[1], bh[3]);
                mma_bf16(acc[mb][2 * np + 0], ah[mb], bl[0], bl[2]);
                mma_bf16(acc[mb][2 * np + 1], ah[mb], bl[1], bl[3]);
                mma_bf16(acc[mb][2 * np + 0], al[mb], bh[0], bh[2]);
                mma_bf16(acc[mb][2 * np + 1], al[mb], bh[1], bh[3]);
            }
        }
        __syncthreads();
    }

    #pragma unroll
    for (int mb = 0; mb < 2; mb++) {
        int r0 = m0 + wm * 32 + mb * 16 + (lane >> 2);
        #pragma unroll
        for (int nb = 0; nb < 8; nb++) {
            int col = n0 + wn * 64 + nb * 8 + ((lane & 3) << 1);
            float b0 = bias[col], b1 = bias[col + 1];
            float x0 = (acc[mb][nb][0] + b0) * scale, x1 = (acc[mb][nb][1] + b1) * scale;
            float x2 = (acc[mb][nb][2] + b0) * scale, x3 = (acc[mb][nb][3] + b1) * scale;
            if (mode == 1) {
                *(float2*)(Cf + (size_t)r0 * Dd + col)       = make_float2(x0, x1);
                *(float2*)(Cf + (size_t)(r0 + 8) * Dd + col) = make_float2(x2, x3);
            } else {
                float l0, l1, l2, l3;
                __nv_bfloat162 h01 = split_hi2(x0, x1, &l0, &l1);
                __nv_bfloat162 h23 = split_hi2(x2, x3, &l2, &l3);
                *(__nv_bfloat162*)(Chi + (size_t)r0 * Dd + col)       = h01;
                *(__nv_bfloat162*)(Chi + (size_t)(r0 + 8) * Dd + col) = h23;
                *(__nv_bfloat162*)(Clo + (size_t)r0 * Dd + col) =
                    __nv_bfloat162(__float2bfloat16_rn(l0), __float2bfloat16_rn(l1));
                *(__nv_bfloat162*)(Clo + (size_t)(r0 + 8) * Dd + col) =
                    __nv_bfloat162(__float2bfloat16_rn(l2), __float2bfloat16_rn(l3));
            }
        }
    }
}

__global__ __launch_bounds__(256, 2) void qkv_tc(const float* __restrict__ bq,
                                                 const float* __restrict__ bk,
                                                 const float* __restrict__ bv) {
    int z = blockIdx.z;
    const __nv_bfloat16* Wh = g_w3h + (size_t)z * 1048576;
    const __nv_bfloat16* Wl = g_w3l + (size_t)z * 1048576;
    const float* bias = (z == 0) ? bq : (z == 1) ? bk : bv;
    __nv_bfloat16* Chi = (z == 0) ? g_qh : (z == 1) ? g_kh : g_vh;
    __nv_bfloat16* Clo = (z == 0) ? g_ql : (z == 1) ? g_kl : g_vl;
    float scale = (z == 0) ? 0.125f : 1.0f;
    hmma_gemm_body(g_dh, g_dl, Wh, Wl, bias, scale, 0, nullptr, Chi, Clo);
}

__global__ __launch_bounds__(256, 2) void out_tc(const float* __restrict__ bo,
                                                 float* __restrict__ out) {
    hmma_gemm_body(g_aoh, g_aol, g_woh, g_wol, bo, 1.0f, 1, out, nullptr, nullptr);
}

// ================= fused attention: scores+traj -> exp -> PV, flash-style =================
// grid (16 i-tiles, 32 bh). CTA: 64 i-rows, 32 j-chunks of 32, cp.async double-buffered K/V.
// dynamic smem 56064 B; 2 CTAs/SM.
#define AQH 0
#define AQL 9216
#define ASTG(st) (18432 + (st) * 18432)   // 4 mats x 4608 per stage
#define ARS 55296
#define AIV 55808
#define ATTN_SMEM 56064

__global__ __launch_bounds__(256, 2) void attn_fused() {
    extern __shared__ __align__(16) char sm[];
    uint32_t ub = smem_to_u32(sm);
    int tid = threadIdx.x, lane = tid & 31, wid = tid >> 5;
    int wm = wid & 3, wn = wid >> 2;
    int g = lane >> 2, t = lane & 3;
    int rsel = lane & 15, csel = (lane >> 4) << 3;
    int bh = blockIdx.y, b = bh >> 4, h = bh & 15;
    int i0 = blockIdx.x << 6;

    const __nv_bfloat16* kvsrc[4] = { g_kh, g_kl, g_vh, g_vl };
    int kvmat = tid >> 6;                 // with s-offset: mat index
    // Q: 2 mats x 64 rows x 8 segs = 1024 slots
    #pragma unroll
    for (int s = 0; s < 4; s++) {
        int idx = tid + (s << 8);
        int mat = idx >> 9, row = (idx >> 3) & 63, seg = idx & 7;
        const __nv_bfloat16* src = (mat == 0 ? g_qh : g_ql) +
            ((size_t)(b * Nn + i0 + row)) * Dd + h * HDd + seg * 8;
        cp16(ub + (mat ? AQL : AQH) + (row * 72 + seg * 8) * 2, src);
    }
    // K/V chunk 0 -> stage 0: 4 mats x 32 rows x 8 segs
    #pragma unroll
    for (int s = 0; s < 4; s++) {
        int idx = tid + (s << 8);
        int mat = idx >> 8, row = (idx >> 3) & 31, seg = idx & 7;
        const __nv_bfloat16* src = kvsrc[mat] + ((size_t)(b * Nn + row)) * Dd + h * HDd + seg * 8;
        cp16(ub + ASTG(0) + mat * 4608 + (row * 72 + seg * 8) * 2, src);
    }
    CP_COMMIT();
    (void)kvmat;

    float pacc[8][4];
    #pragma unroll
    for (int i = 0; i < 8; i++)
        #pragma unroll
        for (int j = 0; j < 4; j++) pacc[i][j] = 0.0f;
    float rs0 = 0.0f, rs1 = 0.0f;

    int i_r0 = i0 + wm * 16 + g;

    for (int c = 0; c < 32; c++) {
        int st = c & 1;
        if (c < 31) {
            int jc1 = (c + 1) << 5, nst = st ^ 1;
            #pragma unroll
            for (int s = 0; s < 4; s++) {
                int idx = tid + (s << 8);
                int mat = idx >> 8, row = (idx >> 3) & 31, seg = idx & 7;
                const __nv_bfloat16* src = kvsrc[mat] +
                    ((size_t)(b * Nn + jc1 + row)) * Dd + h * HDd + seg * 8;
                cp16(ub + ASTG(nst) + mat * 4608 + (row * 72 + seg * 8) * 2, src);
            }
            CP_COMMIT();
            CP_WAIT1();
        } else {
            CP_WAIT0();
        }
        __syncthreads();

        uint32_t kbase = ub + ASTG(st);
        int jc = c << 5;

        // ---- scores: 16i x 16j per warp, 3-pass hi/lo ----
        float sacc0[4] = {0.f, 0.f, 0.f, 0.f};
        float sacc1[4] = {0.f, 0.f, 0.f, 0.f};
        #pragma unroll
        for (int k = 0; k < 4; k++) {
            uint32_t qh[4], ql[4], kh[4], kl[4];
            uint32_t qaddr = (uint32_t)(((wm * 16 + rsel) * 72 + k * 16 + csel) * 2);
            uint32_t kaddr = (uint32_t)(((wn * 16 + rsel) * 72 + k * 16 + csel) * 2);
            ldsm_x4(qh, ub + AQH + qaddr);
            ldsm_x4(ql, ub + AQL + qaddr);
            ldsm_x4(kh, kbase + kaddr);
            ldsm_x4(kl, kbase + 4608 + kaddr);
            mma_bf16(sacc0, qh, kh[0], kh[2]); mma_bf16(sacc1, qh, kh[1], kh[3]);
            mma_bf16(sacc0, qh, kl[0], kl[2]); mma_bf16(sacc1, qh, kl[1], kl[3]);
            mma_bf16(sacc0, ql, kh[0], kh[2]); mma_bf16(sacc1, ql, kh[1], kh[3]);
        }

        // ---- traj bias + exp + split + e_hi store + rowsums ----
        uint32_t ah[4], al[4];
        {
            float* sa = sacc0;
            #pragma unroll
            for (int nt = 0; nt < 2; nt++) {
                int jj = jc + wn * 16 + nt * 8 + 2 * t;
                float2 tv0 = *(const float2*)(g_traj + (size_t)i_r0 * Nn + jj);
                float2 tv1 = *(const float2*)(g_traj + (size_t)(i_r0 + 8) * Nn + jj);
                float e0 = __expf(sa[0] + tv0.x), e1 = __expf(sa[1] + tv0.y);
                float e2 = __expf(sa[2] + tv1.x), e3 = __expf(sa[3] + tv1.y);
                rs0 += e0 + e1; rs1 += e2 + e3;
                __nv_bfloat16 h0 = __float2bfloat16_rn(e0), h1 = __float2bfloat16_rn(e1);
                __nv_bfloat16 h2 = __float2bfloat16_rn(e2), h3 = __float2bfloat16_rn(e3);
                float l0 = e0 - __bfloat162float(h0), l1 = e1 - __bfloat162float(h1);
                float l2 = e2 - __bfloat162float(h2), l3 = e3 - __bfloat162float(h3);
                *(__nv_bfloat162*)(g_eh + ((size_t)bh * Nn + i_r0) * Nn + jj)     = __nv_bfloat162(h0, h1);
                *(__nv_bfloat162*)(g_eh + ((size_t)bh * Nn + i_r0 + 8) * Nn + jj) = __nv_bfloat162(h2, h3);
                ah[nt * 2 + 0] = pack_bf162(h0, h1);
                ah[nt * 2 + 1] = pack_bf162(h2, h3);
                al[nt * 2 + 0] = pack_bf162(__float2bfloat16_rn(l0), __float2bfloat16_rn(l1));
                al[nt * 2 + 1] = pack_bf162(__float2bfloat16_rn(l2), __float2bfloat16_rn(l3));
                sa = sacc1;
            }
        }

        // ---- PV: AO(16i x 64d) += e(16x16) · V(16x64), 3-pass ----
        #pragma unroll
        for (int db = 0; db < 4; db++) {
            uint32_t vh[4], vl[4];
            uint32_t vaddr = (uint32_t)(((wn * 16 + rsel) * 72 + db * 16 + csel) * 2);
            ldsm_x4_t(vh, kbase + 9216 + vaddr);
            ldsm_x4_t(vl, kbase + 13824 + vaddr);
            mma_bf16(pacc[2 * db + 0], ah, vh[0], vh[1]); mma_bf16(pacc[2 * db + 1], ah, vh[2], vh[3]);
            mma_bf16(pacc[2 * db + 0], al, vh[0], vh[1]); mma_bf16(pacc[2 * db + 1], al, vh[2], vh[3]);
            mma_bf16(pacc[2 * db + 0], ah, vl[0], vl[1]); mma_bf16(pacc[2 * db + 1], ah, vl[2], vl[3]);
        }
        __syncthreads();
    }

    // ---- rowsum reduce -> invs ----
    rs0 += __shfl_xor_sync(0xffffffffu, rs0, 1);
    rs0 += __shfl_xor_sync(0xffffffffu, rs0, 2);
    rs1 += __shfl_xor_sync(0xffffffffu, rs1, 1);
    rs1 += __shfl_xor_sync(0xffffffffu, rs1, 2);
    float* s_rs = (float*)(sm + ARS);
    float* s_iv = (float*)(sm + AIV);
    if (t == 0) {
        s_rs[wn * 64 + wm * 16 + g]     = rs0;
        s_rs[wn * 64 + wm * 16 + g + 8] = rs1;
    }
    __syncthreads();
    if (tid < 64) {
        float s = s_rs[tid] + s_rs[64 + tid];
        float inv = 1.0f / s;
        s_iv[tid] = inv;
        g_invs[(size_t)bh * Nn + i0 + tid] = inv;
    }
    __syncthreads();

    // ---- AO cross-warp (wn) reduce, scale by invs, write hi/lo ----
    float* red = (float*)(sm + ASTG(0)) + wm * 1056;   // [16][66] per wm group
    if (wn == 0) {
        #pragma unroll
        for (int nt = 0; nt < 8; nt++) {
            int col = nt * 8 + 2 * t;
            red[g * 66 + col]           = pacc[nt][0];
            red[g * 66 + col + 1]       = pacc[nt][1];
            red[(g + 8) * 66 + col]     = pacc[nt][2];
            red[(g + 8) * 66 + col + 1] = pacc[nt][3];
        }
    }
    __syncthreads();
    if (wn == 1) {
        float inv0 = s_iv[wm * 16 + g], inv1 = s_iv[wm * 16 + g + 8];
        #pragma unroll
        for (int nt = 0; nt < 8; nt++) {
            int col = nt * 8 + 2 * t;
            float x0 = (pacc[nt][0] + red[g * 66 + col])           * inv0;
            float x1 = (pacc[nt][1] + red[g * 66 + col + 1])       * inv0;
            float x2 = (pacc[nt][2] + red[(g + 8) * 66 + col])     * inv1;
            float x3 = (pacc[nt][3] + red[(g + 8) * 66 + col + 1]) * inv1;
            float l0, l1, l2, l3;
            __nv_bfloat162 h01 = split_hi2(x0, x1, &l0, &l1);
            __nv_bfloat162 h23 = split_hi2(x2, x3, &l2, &l3);
            size_t o0 = ((size_t)b * Nn + i_r0) * Dd + h * HDd + col;
            size_t o1 = ((size_t)b * Nn + i_r0 + 8) * Dd + h * HDd + col;
            *(__nv_bfloat162*)(g_aoh + o0) = h01;
            *(__nv_bfloat162*)(g_aoh + o1) = h23;
            *(__nv_bfloat162*)(g_aol + o0) = __nv_bfloat162(__float2bfloat16_rn(l0), __float2bfloat16_rn(l1));
            *(__nv_bfloat162*)(g_aol + o1) = __nv_bfloat162(__float2bfloat16_rn(l2), __float2bfloat16_rn(l3));
        }
    }
}

// ---------------- entropy + certainty from e_hi and invs ----------------
__global__ __launch_bounds__(256) void entropy_kernel(const float* __restrict__ cert,
                                                      float* __restrict__ out_cert) {
    int bi = blockIdx.x;
    int b = bi >> 10, i = bi & 1023;
    int tid = threadIdx.x;

    float a0 = 0.f, a1 = 0.f, a2 = 0.f, a3 = 0.f;
    #pragma unroll
    for (int hh = 0; hh < NHh; hh++) {
        int bh = b * NHh + hh;
        float inv = g_invs[(size_t)bh * Nn + i];
        const __nv_bfloat162* row = (const __nv_bfloat162*)(g_eh + ((size_t)bh * Nn + i) * Nn);
        __nv_bfloat162 v0 = row[tid * 2], v1 = row[tid * 2 + 1];
        a0 += __bfloat162float(v0.x) * inv;
        a1 += __bfloat162float(v0.y) * inv;
        a2 += __bfloat162float(v1.x) * inv;
        a3 += __bfloat162float(v1.y) * inv;
    }
    a0 *= (1.0f / NHh); a1 *= (1.0f / NHh); a2 *= (1.0f / NHh); a3 *= (1.0f / NHh);
    float hl = 0.0f;
    a0 = fmaxf(a0, 1e-10f); hl -= a0 * __logf(a0);
    a1 = fmaxf(a1, 1e-10f); hl -= a1 * __logf(a1);
    a2 = fmaxf(a2, 1e-10f); hl -= a2 * __logf(a2);
    a3 = fmaxf(a3, 1e-10f); hl -= a3 * __logf(a3);
    float H = blk_sum(hl);
    if (tid == 0) {
        float sig = 1.0f / (1.0f + __expf(H - 6.9314718055994531f));   // Hmax = ln(1024)
        out_cert[bi] = fmaxf(cert[bi], sig);
    }
}

// ---------------- trajectory pairwise similarity ----------------
__device__ __forceinline__ float fast_sqrt(float x) {
    return x * rsqrtf(x + 1e-30f);
}

__global__ __launch_bounds__(1024) void traj_kernel(const float* __restrict__ pos,
                                                    const float* __restrict__ quat) {
    __shared__ float Pi[3][BT][32], Pj[3][BT][32];
    __shared__ float Qi[4][BT][32], Qj[4][BT][32];
    int i0 = blockIdx.y * 32, j0 = blockIdx.x * 32;
    int tid = threadIdx.y * 32 + threadIdx.x;

    for (int idx = tid; idx < BT * 32; idx += 1024) {
        int bt = idx >> 5, r = idx & 31;
        size_t pi = ((size_t)bt * Nn + i0 + r) * 3;
        size_t pj = ((size_t)bt * Nn + j0 + r) * 3;
        Pi[0][bt][r] = pos[pi + 0]; Pi[1][bt][r] = pos[pi + 1]; Pi[2][bt][r] = pos[pi + 2];
        Pj[0][bt][r] = pos[pj + 0]; Pj[1][bt][r] = pos[pj + 1]; Pj[2][bt][r] = pos[pj + 2];
        size_t qi = ((size_t)bt * Nn + i0 + r) * 4;
        size_t qj = ((size_t)bt * Nn + j0 + r) * 4;
        Qi[0][bt][r] = quat[qi + 0]; Qi[1][bt][r] = quat[qi + 1];
        Qi[2][bt][r] = quat[qi + 2]; Qi[3][bt][r] = quat[qi + 3];
        Qj[0][bt][r] = quat[qj + 0]; Qj[1][bt][r] = quat[qj + 1];
        Qj[2][bt][r] = quat[qj + 2]; Qj[3][bt][r] = quat[qj + 3];
    }
    __syncthreads();

    int ti = threadIdx.y, tj = threadIdx.x;
    float spd = 0.0f, sqm = 0.0f, sqp = 0.0f;
    #pragma unroll
    for (int bt = 0; bt < BT; bt++) {
        float dx = Pi[0][bt][ti] - Pj[0][bt][tj];
        float dy = Pi[1][bt][ti] - Pj[1][bt][tj];
        float dz = Pi[2][bt][ti] - Pj[2][bt][tj];
        spd += fast_sqrt(dx * dx + dy * dy + dz * dz);
        float a0 = Qi[0][bt][ti], a1 = Qi[1][bt][ti], a2 = Qi[2][bt][ti], a3 = Qi[3][bt][ti];
        float b0 = Qj[0][bt][tj], b1 = Qj[1][bt][tj], b2 = Qj[2][bt][tj], b3 = Qj[3][bt][tj];
        float m0 = a0 - b0, m1 = a1 - b1, m2 = a2 - b2, m3 = a3 - b3;
        float p0 = a0 + b0, p1 = a1 + b1, p2 = a2 + b2, p3 = a3 + b3;
        sqm += fast_sqrt(m0 * m0 + m1 * m1 + m2 * m2 + m3 * m3);
        sqp += fast_sqrt(p0 * p0 + p1 * p1 + p2 * p2 + p3 * p3);
    }
    float pd = spd * (1.0f / BT);
    float qd = fminf(sqm, sqp) * (1.0f / BT);
    g_traj[(size_t)(i0 + ti) * Nn + (j0 + tj)] = __expf(-(pd + qd));
}

// ---------------- row-normalize traj (folds in 0.5 bias scale) ----------------
__global__ __launch_bounds__(256) void traj_norm_kernel() {
    float* row = g_traj + (size_t)blockIdx.x * Nn;
    float4 v = ((const float4*)row)[threadIdx.x];
    float s = blk_sum(v.x + v.y + v.z + v.w);
    float sc = 0.5f / s;
    v.x *= sc; v.y *= sc; v.z *= sc; v.w *= sc;
    ((float4*)row)[threadIdx.x] = v;
}

// ---------------- launch ----------------
extern "C" void kernel_launch(void* const* d_in, const int* in_sizes, int n_in,
                              void* d_out, int out_size) {
    const float* data  = (const float*)d_in[0];
    const float* tpos  = (const float*)d_in[1];
    const float* tquat = (const float*)d_in[2];
    const float* cert  = (const float*)d_in[3];
    const float* Wq = (const float*)d_in[4];  const float* bq = (const float*)d_in[5];
    const float* Wk = (const float*)d_in[6];  const float* bk = (const float*)d_in[7];
    const float* Wv = (const float*)d_in[8];  const float* bv = (const float*)d_in[9];
    const float* Wo = (const float*)d_in[10]; const float* bo = (const float*)d_in[11];
    float* out = (float*)d_out;

    // idempotent, host-side, capture-safe (no enqueue, no allocation)
    cudaFuncSetAttribute(attn_fused, cudaFuncAttributeMaxDynamicSharedMemorySize, ATTN_SMEM);

    split_data<<<2048, 256>>>(data);
    split_w<<<4096, 256>>>(Wq, Wk, Wv, Wo);
    traj_kernel<<<dim3(32, 32), dim3(32, 32)>>>(tpos, tquat);
    traj_norm_kernel<<<Nn, 256>>>();
    qkv_tc<<<dim3(8, 16, 3), 256>>>(bq, bk, bv);
    attn_fused<<<dim3(16, 32), 256, ATTN_SMEM>>>();
    entropy_kernel<<<Bb * Nn, 256>>>(cert, out + (size_t)Bb * Nn * Dd);
    out_tc<<<dim3(8, 16), 256>>>(bo, out);
}